// round 1
// baseline (speedup 1.0000x reference)
#include <cuda_runtime.h>
#include <math.h>

#define BB   8
#define LTOK 32768
#define DD   128
#define BCB  64
#define BSB  512
#define NBL  512      // B*BC
#define KW   6
#define NCH  64       // chunks per batch (512 tokens each)
#define SCALEF 0.08838834764831845f

// ---------------- device scratch (no allocations allowed) ----------------
__device__ float    g_logits[BB*LTOK];
__device__ float    g_e[BB*LTOK];
__device__ float    g_r[BB*LTOK];
__device__ float    g_csum[BB*NCH*DD];
__device__ float    g_prefix[(size_t)BB*LTOK*DD];   // 128 MB
__device__ float    g_conv[(size_t)NBL*BSB*DD];     // 128 MB
__device__ unsigned g_repr[NBL*DD];
__device__ float    g_as[NBL*DD];
__device__ float    g_ao[NBL*DD];
__device__ float    g_wt[DD*KW*DD];                 // transposed conv weights [(i*6+k)*128+o]

// ---------------- helpers ----------------
__device__ __forceinline__ unsigned enc_f(float f) {
    unsigned u = __float_as_uint(f);
    return (u & 0x80000000u) ? ~u : (u | 0x80000000u);
}
__device__ __forceinline__ float dec_f(unsigned u) {
    u = (u & 0x80000000u) ? (u & 0x7fffffffu) : ~u;
    return __uint_as_float(u);
}
__device__ __forceinline__ unsigned long long pack2(float x, float y) {
    unsigned long long r;
    asm("mov.b64 %0, {%1, %2};" : "=l"(r) : "f"(x), "f"(y));
    return r;
}
__device__ __forceinline__ void unpack2(unsigned long long v, float &x, float &y) {
    asm("mov.b64 {%0, %1}, %2;" : "=f"(x), "=f"(y) : "l"(v));
}
__device__ __forceinline__ void ffma2(unsigned long long &c, unsigned long long a, unsigned long long b) {
    asm("fma.rn.f32x2 %0, %1, %2, %0;" : "+l"(c) : "l"(a), "l"(b));
}

// ---------------- K0: transpose conv weights ----------------
__global__ void k_wt(const float* __restrict__ cw) {
    int idx = blockIdx.x * blockDim.x + threadIdx.x;   // 98304 total
    if (idx < DD*KW*DD) {
        int o = idx & 127;
        int ik = idx >> 7;          // i*6+k
        g_wt[idx] = cw[o*768 + ik];
    }
}

// ---------------- K0b: init repr ----------------
__global__ void k_init_repr() {
    int i = blockIdx.x * blockDim.x + threadIdx.x;
    if (i < NBL*DD) g_repr[i] = 0u;
}

// ---------------- K1: logits = silu(x @ w + b) ----------------
__global__ void k_logits(const float* __restrict__ x, const float* __restrict__ w,
                         const float* __restrict__ bl) {
    int gw = blockIdx.x * (blockDim.x >> 5) + (threadIdx.x >> 5);
    int lane = threadIdx.x & 31;
    if (gw >= BB*LTOK) return;
    float4 xv = *(const float4*)&x[(size_t)gw*DD + lane*4];
    float4 wv = *(const float4*)&w[lane*4];
    float s = xv.x*wv.x + xv.y*wv.y + xv.z*wv.z + xv.w*wv.w;
    #pragma unroll
    for (int o = 16; o; o >>= 1) s += __shfl_xor_sync(~0u, s, o);
    if (lane == 0) {
        float z = s + bl[0];
        g_logits[gw] = z / (1.f + expf(-z));
    }
}

// ---------------- K2: per-batch scan (cummax -> exp -> cumsum) ----------------
template<bool MAXOP>
__device__ __forceinline__ float blk_exscan(float v, float* wb) {
    const float ID = MAXOP ? -INFINITY : 0.f;
    int lane = threadIdx.x & 31, wid = threadIdx.x >> 5;
    float x = v;
    #pragma unroll
    for (int o = 1; o < 32; o <<= 1) {
        float y = __shfl_up_sync(~0u, x, o);
        if (lane >= o) x = MAXOP ? fmaxf(x, y) : (x + y);
    }
    if (lane == 31) wb[wid] = x;
    __syncthreads();
    if (wid == 0) {
        float t = wb[lane];
        #pragma unroll
        for (int o = 1; o < 32; o <<= 1) {
            float y = __shfl_up_sync(~0u, t, o);
            if (lane >= o) t = MAXOP ? fmaxf(t, y) : (t + y);
        }
        wb[lane] = t;
    }
    __syncthreads();
    float wpre = (wid == 0) ? ID : wb[wid-1];
    float ex = __shfl_up_sync(~0u, x, 1);
    if (lane == 0) ex = ID;
    float r = MAXOP ? fmaxf(wpre, ex) : (wpre + ex);
    __syncthreads();
    return r;
}

#define SKW(i) ((i) + ((i) >> 5))

__global__ __launch_bounds__(1024, 1) void k_scan() {
    extern __shared__ float S[];          // 33792 floats (skewed 32768)
    __shared__ float wb[32];
    int b = blockIdx.x, t = threadIdx.x;
    const int base = b * LTOK;
    for (int i = t; i < LTOK; i += 1024) S[SKW(i)] = g_logits[base + i];
    __syncthreads();
    // pass 1: local total max
    float tmax = -INFINITY;
    #pragma unroll 8
    for (int u = 0; u < 32; u++) tmax = fmaxf(tmax, S[t*33 + u]);
    float mpre = blk_exscan<true>(tmax, wb);
    // pass 2: running max, e = exp(l - m), local sum
    float m = mpre, ssum = 0.f;
    #pragma unroll 8
    for (int u = 0; u < 32; u++) {
        float l = S[t*33 + u];
        m = fmaxf(m, l);
        float e = expf(l - m);
        S[t*33 + u] = e;
        ssum += e;
    }
    float spre = blk_exscan<false>(ssum, wb);
    float run = spre;
    #pragma unroll 8
    for (int u = 0; u < 32; u++) {
        float e = S[t*33 + u];
        run += e;
        g_e[base + t*32 + u] = e;
        g_r[base + t*32 + u] = 1.f / run;
    }
}

// ---------------- K3a: chunk partial sums of e*x ----------------
__global__ void k_chunksum(const float* __restrict__ x) {
    int ch = blockIdx.x, b = blockIdx.y, d = threadIdx.x;   // 128 threads
    __shared__ float es[BSB];
    size_t base = (size_t)b * LTOK + (size_t)ch * BSB;
    for (int t = d; t < BSB; t += DD) es[t] = g_e[base + t];
    __syncthreads();
    const float* xp = x + base * DD + d;
    float a0 = 0, a1 = 0, a2 = 0, a3 = 0;
    for (int t = 0; t < BSB; t += 4) {
        a0 += es[t+0] * xp[(size_t)(t+0)*DD];
        a1 += es[t+1] * xp[(size_t)(t+1)*DD];
        a2 += es[t+2] * xp[(size_t)(t+2)*DD];
        a3 += es[t+3] * xp[(size_t)(t+3)*DD];
    }
    g_csum[(b*NCH + ch)*DD + d] = (a0 + a1) + (a2 + a3);
}

// ---------------- K3b: exclusive scan of chunk sums ----------------
__global__ void k_chscan() {
    int id = threadIdx.x;            // 1024 = 8*128
    int b = id >> 7, d = id & 127;
    float run = 0.f;
    for (int ch = 0; ch < NCH; ch++) {
        int idx = (b*NCH + ch)*DD + d;
        float v = g_csum[idx];
        g_csum[idx] = run;
        run += v;
    }
}

// ---------------- K3c: finalize prefix = cumsum(e*x)*r + x ----------------
__global__ void k_prefix(const float* __restrict__ x) {
    int ch = blockIdx.x, b = blockIdx.y, d = threadIdx.x;
    __shared__ float es[BSB], rs[BSB];
    size_t base = (size_t)b * LTOK + (size_t)ch * BSB;
    for (int t = d; t < BSB; t += DD) { es[t] = g_e[base + t]; rs[t] = g_r[base + t]; }
    __syncthreads();
    float run = g_csum[(b*NCH + ch)*DD + d];
    const float* xp = x + base * DD + d;
    float* pp = g_prefix + base * DD + d;
    #pragma unroll 4
    for (int t = 0; t < BSB; t++) {
        float xv = xp[(size_t)t*DD];
        run += es[t] * xv;
        pp[(size_t)t*DD] = run * rs[t] + xv;
    }
}

// ---------------- K4: conv1d as tiled GEMM (f32x2 FMA) + fused block max ----------------
#define APITCH 263
__global__ __launch_bounds__(512, 1) void k_conv(const float* __restrict__ cb) {
    __shared__ float As[8 * APITCH];    // 8 in-ch x 261 rows
    __shared__ float Ws[8 * 6 * 128];   // 8 in-ch x 6 k x 128 out
    int n  = blockIdx.y;                // conv block 0..511
    int p0 = blockIdx.x * 256;
    int tid  = threadIdx.x;
    int oidx = tid & 15;                // out group
    int pidx = tid >> 4;                // 0..31 pos group
    size_t tokbase = (size_t)n * BSB;   // n*512 == b*32768 + c*512

    unsigned long long C[8][4];
    #pragma unroll
    for (int u = 0; u < 8; u++)
        #pragma unroll
        for (int v = 0; v < 4; v++) C[u][v] = 0ull;

    for (int ic = 0; ic < 16; ic++) {
        const int i0 = ic * 8;
        __syncthreads();
        for (int e = tid; e < 261*8; e += 512) {
            int r = e >> 3, i = e & 7;
            int pos = p0 + r - 2;
            float v = 0.f;
            if (pos >= 0 && pos < BSB)
                v = g_prefix[(tokbase + pos)*DD + i0 + i];
            As[i*APITCH + r] = v;
        }
        for (int e = tid; e < 6144; e += 512)
            Ws[e] = g_wt[i0*768 + e];
        __syncthreads();

        #pragma unroll 2
        for (int i = 0; i < 8; i++) {
            #pragma unroll
            for (int k = 0; k < KW; k++) {
                const float* wrow = &Ws[(i*6 + k) * 128];
                unsigned long long w2[4];
                #pragma unroll
                for (int v = 0; v < 4; v++)
                    w2[v] = *(const unsigned long long*)(wrow + oidx*2 + v*32);
                #pragma unroll
                for (int u = 0; u < 8; u++) {
                    float a = As[i*APITCH + pidx + u*32 + k];
                    unsigned long long aa = pack2(a, a);
                    #pragma unroll
                    for (int v = 0; v < 4; v++) ffma2(C[u][v], aa, w2[v]);
                }
            }
        }
    }

    // bias, store, fused max
    float2 cbv[4];
    #pragma unroll
    for (int v = 0; v < 4; v++) {
        int o = oidx*2 + v*32;
        cbv[v] = make_float2(cb[o], cb[o+1]);
    }
    float mxx[4], mxy[4];
    #pragma unroll
    for (int v = 0; v < 4; v++) { mxx[v] = -INFINITY; mxy[v] = -INFINITY; }
    #pragma unroll
    for (int u = 0; u < 8; u++) {
        size_t row = ((size_t)n * BSB + p0 + pidx + u*32) * DD;
        #pragma unroll
        for (int v = 0; v < 4; v++) {
            float cx, cy;
            unpack2(C[u][v], cx, cy);
            cx += cbv[v].x; cy += cbv[v].y;
            int o = oidx*2 + v*32;
            *(float2*)&g_conv[row + o] = make_float2(cx, cy);
            mxx[v] = fmaxf(mxx[v], cx);
            mxy[v] = fmaxf(mxy[v], cy);
        }
    }
    #pragma unroll
    for (int v = 0; v < 4; v++) {
        int o = oidx*2 + v*32;
        atomicMax(&g_repr[n*DD + o],     enc_f(mxx[v]));
        atomicMax(&g_repr[n*DD + o + 1], enc_f(mxy[v]));
    }
}

// ---------------- K6: a_s = attn(block_repr, blocks_c, blocks_c) ----------------
__global__ void k_attn_s() {
    int n = blockIdx.x, tid = threadIdx.x;      // 128 threads
    int lane = tid & 31, w = tid >> 5;
    __shared__ float s[BSB];
    __shared__ float red[128];
    float4 q4;
    q4.x = dec_f(g_repr[n*DD + lane*4 + 0]);
    q4.y = dec_f(g_repr[n*DD + lane*4 + 1]);
    q4.z = dec_f(g_repr[n*DD + lane*4 + 2]);
    q4.w = dec_f(g_repr[n*DD + lane*4 + 3]);
    const float* kv = g_conv + (size_t)n * BSB * DD;
    for (int j = w; j < BSB; j += 4) {
        float4 k4 = *(const float4*)&kv[(size_t)j*DD + lane*4];
        float p = q4.x*k4.x + q4.y*k4.y + q4.z*k4.z + q4.w*k4.w;
        #pragma unroll
        for (int o = 16; o; o >>= 1) p += __shfl_xor_sync(~0u, p, o);
        if (lane == 0) s[j] = p * SCALEF;
    }
    __syncthreads();
    float mx = -INFINITY;
    for (int j = tid; j < BSB; j += 128) mx = fmaxf(mx, s[j]);
    red[tid] = mx; __syncthreads();
    for (int st = 64; st; st >>= 1) { if (tid < st) red[tid] = fmaxf(red[tid], red[tid+st]); __syncthreads(); }
    float M = red[0]; __syncthreads();
    float sm = 0.f;
    for (int j = tid; j < BSB; j += 128) { float e = expf(s[j] - M); s[j] = e; sm += e; }
    red[tid] = sm; __syncthreads();
    for (int st = 64; st; st >>= 1) { if (tid < st) red[tid] += red[tid+st]; __syncthreads(); }
    float SUM = red[0]; __syncthreads();
    float acc = 0.f;
    #pragma unroll 4
    for (int j = 0; j < BSB; j++) acc += s[j] * kv[(size_t)j*DD + tid];
    g_as[n*DD + tid] = acc / SUM;
}

// ---------------- K7: a_o = attn(block_repr, xbo, xbo) ----------------
__global__ void k_attn_o() {
    int n = blockIdx.x, tid = threadIdx.x;      // 128 threads
    int lane = tid & 31, w = tid >> 5;
    int bq = n >> 6, c = n & 63;
    __shared__ float s[128];
    __shared__ float red[128];
    float4 q4;
    q4.x = dec_f(g_repr[n*DD + lane*4 + 0]);
    q4.y = dec_f(g_repr[n*DD + lane*4 + 1]);
    q4.z = dec_f(g_repr[n*DD + lane*4 + 2]);
    q4.w = dec_f(g_repr[n*DD + lane*4 + 3]);
    for (int j = w; j < 128; j += 4) {
        int tt = 448 + c*BSB + j; if (tt > LTOK-1) tt = LTOK-1;
        const float* row = &g_prefix[((size_t)bq*LTOK + tt)*DD];
        float4 k4 = *(const float4*)&row[lane*4];
        float p = q4.x*k4.x + q4.y*k4.y + q4.z*k4.z + q4.w*k4.w;
        #pragma unroll
        for (int o = 16; o; o >>= 1) p += __shfl_xor_sync(~0u, p, o);
        if (lane == 0) s[j] = p * SCALEF;
    }
    __syncthreads();
    red[tid] = s[tid]; __syncthreads();
    for (int st = 64; st; st >>= 1) { if (tid < st) red[tid] = fmaxf(red[tid], red[tid+st]); __syncthreads(); }
    float M = red[0]; __syncthreads();
    float e = expf(s[tid] - M); s[tid] = e;
    red[tid] = e; __syncthreads();
    for (int st = 64; st; st >>= 1) { if (tid < st) red[tid] += red[tid+st]; __syncthreads(); }
    float SUM = red[0]; __syncthreads();
    float acc = 0.f;
    for (int j = 0; j < 128; j++) {
        int tt = 448 + c*BSB + j; if (tt > LTOK-1) tt = LTOK-1;
        acc += s[j] * g_prefix[((size_t)bq*LTOK + tt)*DD + tid];
    }
    g_ao[n*DD + tid] = acc / SUM;
}

// ---------------- K8: fusion GEMV ----------------
__global__ void k_fuse(const float* __restrict__ fw, const float* __restrict__ fb,
                       float* __restrict__ out, int out_size) {
    int n = blockIdx.x, o = threadIdx.x;    // 128 threads
    __shared__ float f[384];
    f[o]       = g_as[n*DD + o];
    f[128 + o] = g_ao[n*DD + o];
    f[256 + o] = dec_f(g_repr[n*DD + o]);
    __syncthreads();
    float acc = fb[o];
    #pragma unroll 4
    for (int i = 0; i < 384; i++) acc += f[i] * fw[i*DD + o];
    for (int off = 0; off + NBL*DD <= out_size; off += NBL*DD)
        out[off + n*DD + o] = acc;
}

// ---------------- launch ----------------
extern "C" void kernel_launch(void* const* d_in, const int* in_sizes, int n_in,
                              void* d_out, int out_size) {
    const float* x        = (const float*)d_in[0];
    const float* w_lw     = (const float*)d_in[1];
    const float* b_lw     = (const float*)d_in[2];
    const float* conv_w   = (const float*)d_in[3];
    const float* conv_b   = (const float*)d_in[4];
    const float* fusion_w = (const float*)d_in[5];
    const float* fusion_b = (const float*)d_in[6];
    float* out = (float*)d_out;

    cudaFuncSetAttribute(k_scan, cudaFuncAttributeMaxDynamicSharedMemorySize, 33792 * 4);

    k_wt<<<96, 1024>>>(conv_w);
    k_init_repr<<<64, 1024>>>();
    k_logits<<<BB*LTOK/8, 256>>>(x, w_lw, b_lw);
    k_scan<<<BB, 1024, 33792 * 4>>>();
    k_chunksum<<<dim3(NCH, BB), 128>>>(x);
    k_chscan<<<1, 1024>>>();
    k_prefix<<<dim3(NCH, BB), 128>>>(x);
    k_conv<<<dim3(2, NBL), 512>>>(conv_b);
    k_attn_s<<<NBL, 128>>>();
    k_attn_o<<<NBL, 128>>>();
    k_fuse<<<NBL, 128>>>(fusion_w, fusion_b, out, out_size);
}

// round 2
// speedup vs baseline: 1.0006x; 1.0006x over previous
#include <cuda_runtime.h>
#include <math.h>

#define BB   8
#define LTOK 32768
#define DD   128
#define BCB  64
#define BSB  512
#define NBL  512      // B*BC
#define KW   6
#define NCH  64       // chunks per batch (512 tokens each)
#define SCALEF 0.08838834764831845f

// ---------------- device scratch (no allocations allowed) ----------------
__device__ float    g_logits[BB*LTOK];
__device__ float    g_e[BB*LTOK];
__device__ float    g_r[BB*LTOK];
__device__ float    g_csum[BB*NCH*DD];
__device__ float    g_prefix[(size_t)BB*LTOK*DD];   // 128 MB
__device__ float    g_conv[(size_t)NBL*BSB*DD];     // 128 MB
__device__ unsigned g_repr[NBL*DD];
__device__ float    g_as[NBL*DD];
__device__ float    g_ao[NBL*DD];
__device__ float    g_wt[DD*KW*DD];                 // transposed conv weights [(i*6+k)*128+o]

// ---------------- helpers ----------------
__device__ __forceinline__ unsigned enc_f(float f) {
    unsigned u = __float_as_uint(f);
    return (u & 0x80000000u) ? ~u : (u | 0x80000000u);
}
__device__ __forceinline__ float dec_f(unsigned u) {
    u = (u & 0x80000000u) ? (u & 0x7fffffffu) : ~u;
    return __uint_as_float(u);
}
__device__ __forceinline__ unsigned long long pack2(float x, float y) {
    unsigned long long r;
    asm("mov.b64 %0, {%1, %2};" : "=l"(r) : "f"(x), "f"(y));
    return r;
}
__device__ __forceinline__ void unpack2(unsigned long long v, float &x, float &y) {
    asm("mov.b64 {%0, %1}, %2;" : "=f"(x), "=f"(y) : "l"(v));
}
__device__ __forceinline__ void ffma2(unsigned long long &c, unsigned long long a, unsigned long long b) {
    asm("fma.rn.f32x2 %0, %1, %2, %0;" : "+l"(c) : "l"(a), "l"(b));
}

// ---------------- K0: transpose conv weights ----------------
__global__ void k_wt(const float* __restrict__ cw) {
    int idx = blockIdx.x * blockDim.x + threadIdx.x;   // 98304 total
    if (idx < DD*KW*DD) {
        int o = idx & 127;
        int ik = idx >> 7;          // i*6+k
        g_wt[idx] = cw[o*768 + ik];
    }
}

// ---------------- K0b: init repr ----------------
__global__ void k_init_repr() {
    int i = blockIdx.x * blockDim.x + threadIdx.x;
    if (i < NBL*DD) g_repr[i] = 0u;
}

// ---------------- K1: logits = silu(x @ w + b) ----------------
__global__ void k_logits(const float* __restrict__ x, const float* __restrict__ w,
                         const float* __restrict__ bl) {
    int gw = blockIdx.x * (blockDim.x >> 5) + (threadIdx.x >> 5);
    int lane = threadIdx.x & 31;
    if (gw >= BB*LTOK) return;
    float4 xv = *(const float4*)&x[(size_t)gw*DD + lane*4];
    float4 wv = *(const float4*)&w[lane*4];
    float s = xv.x*wv.x + xv.y*wv.y + xv.z*wv.z + xv.w*wv.w;
    #pragma unroll
    for (int o = 16; o; o >>= 1) s += __shfl_xor_sync(~0u, s, o);
    if (lane == 0) {
        float z = s + bl[0];
        g_logits[gw] = z / (1.f + expf(-z));
    }
}

// ---------------- K2: per-batch scan (cummax -> exp -> cumsum) ----------------
template<bool MAXOP>
__device__ __forceinline__ float blk_exscan(float v, float* wb) {
    const float ID = MAXOP ? -INFINITY : 0.f;
    int lane = threadIdx.x & 31, wid = threadIdx.x >> 5;
    float x = v;
    #pragma unroll
    for (int o = 1; o < 32; o <<= 1) {
        float y = __shfl_up_sync(~0u, x, o);
        if (lane >= o) x = MAXOP ? fmaxf(x, y) : (x + y);
    }
    if (lane == 31) wb[wid] = x;
    __syncthreads();
    if (wid == 0) {
        float t = wb[lane];
        #pragma unroll
        for (int o = 1; o < 32; o <<= 1) {
            float y = __shfl_up_sync(~0u, t, o);
            if (lane >= o) t = MAXOP ? fmaxf(t, y) : (t + y);
        }
        wb[lane] = t;
    }
    __syncthreads();
    float wpre = (wid == 0) ? ID : wb[wid-1];
    float ex = __shfl_up_sync(~0u, x, 1);
    if (lane == 0) ex = ID;
    float r = MAXOP ? fmaxf(wpre, ex) : (wpre + ex);
    __syncthreads();
    return r;
}

#define SKW(i) ((i) + ((i) >> 5))

__global__ __launch_bounds__(1024, 1) void k_scan() {
    extern __shared__ float S[];          // 33792 floats (skewed 32768)
    __shared__ float wb[32];
    int b = blockIdx.x, t = threadIdx.x;
    const int base = b * LTOK;
    for (int i = t; i < LTOK; i += 1024) S[SKW(i)] = g_logits[base + i];
    __syncthreads();
    // pass 1: local total max
    float tmax = -INFINITY;
    #pragma unroll 8
    for (int u = 0; u < 32; u++) tmax = fmaxf(tmax, S[t*33 + u]);
    float mpre = blk_exscan<true>(tmax, wb);
    // pass 2: running max, e = exp(l - m), local sum
    float m = mpre, ssum = 0.f;
    #pragma unroll 8
    for (int u = 0; u < 32; u++) {
        float l = S[t*33 + u];
        m = fmaxf(m, l);
        float e = expf(l - m);
        S[t*33 + u] = e;
        ssum += e;
    }
    float spre = blk_exscan<false>(ssum, wb);
    float run = spre;
    #pragma unroll 8
    for (int u = 0; u < 32; u++) {
        float e = S[t*33 + u];
        run += e;
        g_e[base + t*32 + u] = e;
        g_r[base + t*32 + u] = 1.f / run;
    }
}

// ---------------- K3a: chunk partial sums of e*x ----------------
__global__ void k_chunksum(const float* __restrict__ x) {
    int ch = blockIdx.x, b = blockIdx.y, d = threadIdx.x;   // 128 threads
    __shared__ float es[BSB];
    size_t base = (size_t)b * LTOK + (size_t)ch * BSB;
    for (int t = d; t < BSB; t += DD) es[t] = g_e[base + t];
    __syncthreads();
    const float* xp = x + base * DD + d;
    float a0 = 0, a1 = 0, a2 = 0, a3 = 0;
    for (int t = 0; t < BSB; t += 4) {
        a0 += es[t+0] * xp[(size_t)(t+0)*DD];
        a1 += es[t+1] * xp[(size_t)(t+1)*DD];
        a2 += es[t+2] * xp[(size_t)(t+2)*DD];
        a3 += es[t+3] * xp[(size_t)(t+3)*DD];
    }
    g_csum[(b*NCH + ch)*DD + d] = (a0 + a1) + (a2 + a3);
}

// ---------------- K3b: exclusive scan of chunk sums ----------------
__global__ void k_chscan() {
    int id = threadIdx.x;            // 1024 = 8*128
    int b = id >> 7, d = id & 127;
    float run = 0.f;
    for (int ch = 0; ch < NCH; ch++) {
        int idx = (b*NCH + ch)*DD + d;
        float v = g_csum[idx];
        g_csum[idx] = run;
        run += v;
    }
}

// ---------------- K3c: finalize prefix = cumsum(e*x)*r + x ----------------
__global__ void k_prefix(const float* __restrict__ x) {
    int ch = blockIdx.x, b = blockIdx.y, d = threadIdx.x;
    __shared__ float es[BSB], rs[BSB];
    size_t base = (size_t)b * LTOK + (size_t)ch * BSB;
    for (int t = d; t < BSB; t += DD) { es[t] = g_e[base + t]; rs[t] = g_r[base + t]; }
    __syncthreads();
    float run = g_csum[(b*NCH + ch)*DD + d];
    const float* xp = x + base * DD + d;
    float* pp = g_prefix + base * DD + d;
    #pragma unroll 4
    for (int t = 0; t < BSB; t++) {
        float xv = xp[(size_t)t*DD];
        run += es[t] * xv;
        pp[(size_t)t*DD] = run * rs[t] + xv;
    }
}

// ---------------- K4: conv1d as tiled GEMM (f32x2 FMA) + fused block max ----------------
#define APITCH 263
__global__ __launch_bounds__(512, 1) void k_conv(const float* __restrict__ cb) {
    __shared__ float As[8 * APITCH];    // 8 in-ch x 261 rows
    __shared__ float Ws[8 * 6 * 128];   // 8 in-ch x 6 k x 128 out
    int n  = blockIdx.y;                // conv block 0..511
    int p0 = blockIdx.x * 256;
    int tid  = threadIdx.x;
    int oidx = tid & 15;                // out group
    int pidx = tid >> 4;                // 0..31 pos group
    size_t tokbase = (size_t)n * BSB;   // n*512 == b*32768 + c*512

    unsigned long long C[8][4];
    #pragma unroll
    for (int u = 0; u < 8; u++)
        #pragma unroll
        for (int v = 0; v < 4; v++) C[u][v] = 0ull;

    for (int ic = 0; ic < 16; ic++) {
        const int i0 = ic * 8;
        __syncthreads();
        for (int e = tid; e < 261*8; e += 512) {
            int r = e >> 3, i = e & 7;
            int pos = p0 + r - 2;
            float v = 0.f;
            if (pos >= 0 && pos < BSB)
                v = g_prefix[(tokbase + pos)*DD + i0 + i];
            As[i*APITCH + r] = v;
        }
        for (int e = tid; e < 6144; e += 512)
            Ws[e] = g_wt[i0*768 + e];
        __syncthreads();

        #pragma unroll 2
        for (int i = 0; i < 8; i++) {
            #pragma unroll
            for (int k = 0; k < KW; k++) {
                const float* wrow = &Ws[(i*6 + k) * 128];
                unsigned long long w2[4];
                #pragma unroll
                for (int v = 0; v < 4; v++)
                    w2[v] = *(const unsigned long long*)(wrow + oidx*2 + v*32);
                #pragma unroll
                for (int u = 0; u < 8; u++) {
                    float a = As[i*APITCH + pidx + u*32 + k];
                    unsigned long long aa = pack2(a, a);
                    #pragma unroll
                    for (int v = 0; v < 4; v++) ffma2(C[u][v], aa, w2[v]);
                }
            }
        }
    }

    // bias, store, fused max
    float2 cbv[4];
    #pragma unroll
    for (int v = 0; v < 4; v++) {
        int o = oidx*2 + v*32;
        cbv[v] = make_float2(cb[o], cb[o+1]);
    }
    float mxx[4], mxy[4];
    #pragma unroll
    for (int v = 0; v < 4; v++) { mxx[v] = -INFINITY; mxy[v] = -INFINITY; }
    #pragma unroll
    for (int u = 0; u < 8; u++) {
        size_t row = ((size_t)n * BSB + p0 + pidx + u*32) * DD;
        #pragma unroll
        for (int v = 0; v < 4; v++) {
            float cx, cy;
            unpack2(C[u][v], cx, cy);
            cx += cbv[v].x; cy += cbv[v].y;
            int o = oidx*2 + v*32;
            *(float2*)&g_conv[row + o] = make_float2(cx, cy);
            mxx[v] = fmaxf(mxx[v], cx);
            mxy[v] = fmaxf(mxy[v], cy);
        }
    }
    #pragma unroll
    for (int v = 0; v < 4; v++) {
        int o = oidx*2 + v*32;
        atomicMax(&g_repr[n*DD + o],     enc_f(mxx[v]));
        atomicMax(&g_repr[n*DD + o + 1], enc_f(mxy[v]));
    }
}

// ---------------- K6: a_s = attn(block_repr, blocks_c, blocks_c) ----------------
__global__ void k_attn_s() {
    int n = blockIdx.x, tid = threadIdx.x;      // 128 threads
    int lane = tid & 31, w = tid >> 5;
    __shared__ float s[BSB];
    __shared__ float red[128];
    float4 q4;
    q4.x = dec_f(g_repr[n*DD + lane*4 + 0]);
    q4.y = dec_f(g_repr[n*DD + lane*4 + 1]);
    q4.z = dec_f(g_repr[n*DD + lane*4 + 2]);
    q4.w = dec_f(g_repr[n*DD + lane*4 + 3]);
    const float* kv = g_conv + (size_t)n * BSB * DD;
    for (int j = w; j < BSB; j += 4) {
        float4 k4 = *(const float4*)&kv[(size_t)j*DD + lane*4];
        float p = q4.x*k4.x + q4.y*k4.y + q4.z*k4.z + q4.w*k4.w;
        #pragma unroll
        for (int o = 16; o; o >>= 1) p += __shfl_xor_sync(~0u, p, o);
        if (lane == 0) s[j] = p * SCALEF;
    }
    __syncthreads();
    float mx = -INFINITY;
    for (int j = tid; j < BSB; j += 128) mx = fmaxf(mx, s[j]);
    red[tid] = mx; __syncthreads();
    for (int st = 64; st; st >>= 1) { if (tid < st) red[tid] = fmaxf(red[tid], red[tid+st]); __syncthreads(); }
    float M = red[0]; __syncthreads();
    float sm = 0.f;
    for (int j = tid; j < BSB; j += 128) { float e = expf(s[j] - M); s[j] = e; sm += e; }
    red[tid] = sm; __syncthreads();
    for (int st = 64; st; st >>= 1) { if (tid < st) red[tid] += red[tid+st]; __syncthreads(); }
    float SUM = red[0]; __syncthreads();
    float acc = 0.f;
    #pragma unroll 4
    for (int j = 0; j < BSB; j++) acc += s[j] * kv[(size_t)j*DD + tid];
    g_as[n*DD + tid] = acc / SUM;
}

// ---------------- K7: a_o = attn(block_repr, xbo, xbo) ----------------
__global__ void k_attn_o() {
    int n = blockIdx.x, tid = threadIdx.x;      // 128 threads
    int lane = tid & 31, w = tid >> 5;
    int bq = n >> 6, c = n & 63;
    __shared__ float s[128];
    __shared__ float red[128];
    float4 q4;
    q4.x = dec_f(g_repr[n*DD + lane*4 + 0]);
    q4.y = dec_f(g_repr[n*DD + lane*4 + 1]);
    q4.z = dec_f(g_repr[n*DD + lane*4 + 2]);
    q4.w = dec_f(g_repr[n*DD + lane*4 + 3]);
    for (int j = w; j < 128; j += 4) {
        int tt = 448 + c*BSB + j; if (tt > LTOK-1) tt = LTOK-1;
        const float* row = &g_prefix[((size_t)bq*LTOK + tt)*DD];
        float4 k4 = *(const float4*)&row[lane*4];
        float p = q4.x*k4.x + q4.y*k4.y + q4.z*k4.z + q4.w*k4.w;
        #pragma unroll
        for (int o = 16; o; o >>= 1) p += __shfl_xor_sync(~0u, p, o);
        if (lane == 0) s[j] = p * SCALEF;
    }
    __syncthreads();
    red[tid] = s[tid]; __syncthreads();
    for (int st = 64; st; st >>= 1) { if (tid < st) red[tid] = fmaxf(red[tid], red[tid+st]); __syncthreads(); }
    float M = red[0]; __syncthreads();
    float e = expf(s[tid] - M); s[tid] = e;
    red[tid] = e; __syncthreads();
    for (int st = 64; st; st >>= 1) { if (tid < st) red[tid] += red[tid+st]; __syncthreads(); }
    float SUM = red[0]; __syncthreads();
    float acc = 0.f;
    for (int j = 0; j < 128; j++) {
        int tt = 448 + c*BSB + j; if (tt > LTOK-1) tt = LTOK-1;
        acc += s[j] * g_prefix[((size_t)bq*LTOK + tt)*DD + tid];
    }
    g_ao[n*DD + tid] = acc / SUM;
}

// ---------------- K8: fusion GEMV ----------------
__global__ void k_fuse(const float* __restrict__ fw, const float* __restrict__ fb,
                       float* __restrict__ out, int out_size) {
    int n = blockIdx.x, o = threadIdx.x;    // 128 threads
    __shared__ float f[384];
    f[o]       = g_as[n*DD + o];
    f[128 + o] = g_ao[n*DD + o];
    f[256 + o] = dec_f(g_repr[n*DD + o]);
    __syncthreads();
    float acc = fb[o];
    #pragma unroll 4
    for (int i = 0; i < 384; i++) acc += f[i] * fw[i*DD + o];
    for (int off = 0; off + NBL*DD <= out_size; off += NBL*DD)
        out[off + n*DD + o] = acc;
}

// ---------------- launch ----------------
extern "C" void kernel_launch(void* const* d_in, const int* in_sizes, int n_in,
                              void* d_out, int out_size) {
    const float* x        = (const float*)d_in[0];
    const float* w_lw     = (const float*)d_in[1];
    const float* b_lw     = (const float*)d_in[2];
    const float* conv_w   = (const float*)d_in[3];
    const float* conv_b   = (const float*)d_in[4];
    const float* fusion_w = (const float*)d_in[5];
    const float* fusion_b = (const float*)d_in[6];
    float* out = (float*)d_out;

    cudaFuncSetAttribute(k_scan, cudaFuncAttributeMaxDynamicSharedMemorySize, 33792 * 4);

    k_wt<<<96, 1024>>>(conv_w);
    k_init_repr<<<64, 1024>>>();
    k_logits<<<BB*LTOK/8, 256>>>(x, w_lw, b_lw);
    k_scan<<<BB, 1024, 33792 * 4>>>();
    k_chunksum<<<dim3(NCH, BB), 128>>>(x);
    k_chscan<<<1, 1024>>>();
    k_prefix<<<dim3(NCH, BB), 128>>>(x);
    k_conv<<<dim3(2, NBL), 512>>>(conv_b);
    k_attn_s<<<NBL, 128>>>();
    k_attn_o<<<NBL, 128>>>();
    k_fuse<<<NBL, 128>>>(fusion_w, fusion_b, out, out_size);
}

// round 5
// speedup vs baseline: 1.5977x; 1.5968x over previous
#include <cuda_runtime.h>
#include <cuda_bf16.h>
#include <math.h>
#include <stdint.h>

#define BB   8
#define LTOK 32768
#define DD   128
#define BSB  512
#define NBL  512
#define KW   6
#define NCH  64
#define SCALEF 0.08838834764831845f

// ---------------- device scratch ----------------
__device__ float    g_logits[BB*LTOK];
__device__ float    g_e[BB*LTOK];
__device__ float    g_r[BB*LTOK];
__device__ float    g_cm[BB*NCH];
__device__ float    g_cm0[BB*NCH];
__device__ float    g_cs[BB*NCH];
__device__ float    g_cp0[BB*NCH];
__device__ float    g_csum[BB*NCH*DD];
__device__ __align__(16) __nv_bfloat16 g_ph[(size_t)BB*LTOK*DD];   // prefix hi
__device__ __align__(16) __nv_bfloat16 g_pl[(size_t)BB*LTOK*DD];   // prefix lo
__device__ float    g_conv[(size_t)NBL*BSB*DD];
__device__ unsigned g_repr[NBL*DD];
__device__ float    g_as[NBL*DD];
__device__ float    g_ao[NBL*DD];
__device__ __align__(16) __nv_bfloat16 g_wh[KW*DD*DD];  // [k][o][i]
__device__ __align__(16) __nv_bfloat16 g_wl[KW*DD*DD];

// ---------------- helpers ----------------
__device__ __forceinline__ unsigned enc_f(float f) {
    unsigned u = __float_as_uint(f);
    return (u & 0x80000000u) ? ~u : (u | 0x80000000u);
}
__device__ __forceinline__ float dec_f(unsigned u) {
    u = (u & 0x80000000u) ? (u & 0x7fffffffu) : ~u;
    return __uint_as_float(u);
}
__device__ __forceinline__ uint32_t smem_u32(const void* p) {
    uint32_t a;
    asm("{ .reg .u64 t; cvta.to.shared.u64 t, %1; cvt.u32.u64 %0, t; }" : "=r"(a) : "l"(p));
    return a;
}
__device__ __forceinline__ void ldsm_x4(uint32_t* r, uint32_t addr) {
    asm volatile("ldmatrix.sync.aligned.m8n8.x4.shared.b16 {%0,%1,%2,%3}, [%4];"
        : "=r"(r[0]), "=r"(r[1]), "=r"(r[2]), "=r"(r[3]) : "r"(addr));
}
__device__ __forceinline__ void mma16816(float* c, const uint32_t* a, uint32_t b0, uint32_t b1) {
    asm volatile(
        "mma.sync.aligned.m16n8k16.row.col.f32.bf16.bf16.f32 "
        "{%0,%1,%2,%3}, {%4,%5,%6,%7}, {%8,%9}, {%0,%1,%2,%3};"
        : "+f"(c[0]), "+f"(c[1]), "+f"(c[2]), "+f"(c[3])
        : "r"(a[0]), "r"(a[1]), "r"(a[2]), "r"(a[3]), "r"(b0), "r"(b1));
}

// ---------------- K0: split conv weights to bf16 hi/lo [k][o][i] ----------------
__global__ void k_wt(const float* __restrict__ cw) {
    int idx = blockIdx.x * blockDim.x + threadIdx.x;
    if (idx < KW*DD*DD) {
        int i = idx & 127;
        int r = idx >> 7;
        int o = r & 127;
        int kk = r >> 7;
        float v = cw[o*768 + i*6 + kk];
        __nv_bfloat16 h = __float2bfloat16(v);
        g_wh[idx] = h;
        g_wl[idx] = __float2bfloat16(v - __bfloat162float(h));
    }
}

__global__ void k_init_repr() {
    int i = blockIdx.x * blockDim.x + threadIdx.x;
    if (i < NBL*DD) g_repr[i] = 0u;
}

// ---------------- K1: logits = silu(x @ w + b) ----------------
__global__ void k_logits(const float* __restrict__ x, const float* __restrict__ w,
                         const float* __restrict__ bl) {
    int gw = blockIdx.x * (blockDim.x >> 5) + (threadIdx.x >> 5);
    int lane = threadIdx.x & 31;
    if (gw >= BB*LTOK) return;
    float4 xv = *(const float4*)&x[(size_t)gw*DD + lane*4];
    float4 wv = *(const float4*)&w[lane*4];
    float s = xv.x*wv.x + xv.y*wv.y + xv.z*wv.z + xv.w*wv.w;
    #pragma unroll
    for (int o = 16; o; o >>= 1) s += __shfl_xor_sync(~0u, s, o);
    if (lane == 0) {
        float z = s + bl[0];
        g_logits[gw] = z / (1.f + expf(-z));
    }
}

// ---------------- parallel scan (chunked) ----------------
template<bool MX>
__device__ __forceinline__ float iscan512(float v, float* ws) {
    int lane = threadIdx.x & 31, w = threadIdx.x >> 5;
    float x = v;
    #pragma unroll
    for (int o = 1; o < 32; o <<= 1) {
        float y = __shfl_up_sync(~0u, x, o);
        if (lane >= o) x = MX ? fmaxf(x, y) : (x + y);
    }
    if (lane == 31) ws[w] = x;
    __syncthreads();
    if (w == 0 && lane < 16) {
        float t = ws[lane];
        #pragma unroll
        for (int o = 1; o < 16; o <<= 1) {
            float y = __shfl_up_sync(0xFFFFu, t, o);
            if (lane >= o) t = MX ? fmaxf(t, y) : (t + y);
        }
        ws[lane] = t;
    }
    __syncthreads();
    if (w > 0) {
        float pre = ws[w-1];
        x = MX ? fmaxf(x, pre) : (x + pre);
    }
    return x;
}

__global__ void k_cmax() {
    __shared__ float red[256];
    int c = blockIdx.x, b = blockIdx.y, t = threadIdx.x;
    int base = b*LTOK + c*BSB;
    float v = fmaxf(g_logits[base + t], g_logits[base + t + 256]);
    red[t] = v; __syncthreads();
    for (int st = 128; st; st >>= 1) { if (t < st) red[t] = fmaxf(red[t], red[t+st]); __syncthreads(); }
    if (t == 0) g_cm[b*NCH + c] = red[0];
}
__global__ void k_cmaxscan() {
    int b = threadIdx.x; if (b >= BB) return;
    float run = -INFINITY;
    for (int c = 0; c < NCH; c++) {
        g_cm0[b*NCH + c] = run;
        run = fmaxf(run, g_cm[b*NCH + c]);
    }
}
__global__ __launch_bounds__(512) void k_escan() {
    __shared__ float ws[16];
    int c = blockIdx.x, b = blockIdx.y, t = threadIdx.x;
    int base = b*LTOK + c*BSB;
    float l = g_logits[base + t];
    float lm = iscan512<true>(l, ws);
    float M = fmaxf(lm, g_cm0[b*NCH + c]);
    float e = expf(l - M);
    g_e[base + t] = e;
    __syncthreads();
    float S = iscan512<false>(e, ws);
    if (t == 511) g_cs[b*NCH + c] = S;
}
__global__ void k_csscan() {
    int b = threadIdx.x; if (b >= BB) return;
    float run = 0.f;
    for (int c = 0; c < NCH; c++) {
        g_cp0[b*NCH + c] = run;
        run += g_cs[b*NCH + c];
    }
}
__global__ __launch_bounds__(512) void k_rfin() {
    __shared__ float ws[16];
    int c = blockIdx.x, b = blockIdx.y, t = threadIdx.x;
    int base = b*LTOK + c*BSB;
    float e = g_e[base + t];
    float P = iscan512<false>(e, ws) + g_cp0[b*NCH + c];
    g_r[base + t] = 1.f / P;
}

// ---------------- K3a: chunk partial sums of e*x ----------------
__global__ void k_chunksum(const float* __restrict__ x) {
    int ch = blockIdx.x, b = blockIdx.y, d = threadIdx.x;
    __shared__ float es[BSB];
    size_t base = (size_t)b * LTOK + (size_t)ch * BSB;
    for (int t = d; t < BSB; t += DD) es[t] = g_e[base + t];
    __syncthreads();
    const float* xp = x + base * DD + d;
    float a0 = 0, a1 = 0, a2 = 0, a3 = 0;
    for (int t = 0; t < BSB; t += 4) {
        a0 += es[t+0] * xp[(size_t)(t+0)*DD];
        a1 += es[t+1] * xp[(size_t)(t+1)*DD];
        a2 += es[t+2] * xp[(size_t)(t+2)*DD];
        a3 += es[t+3] * xp[(size_t)(t+3)*DD];
    }
    g_csum[(b*NCH + ch)*DD + d] = (a0 + a1) + (a2 + a3);
}

__global__ void k_chscan() {
    int id = threadIdx.x;            // 1024 = 8*128
    int b = id >> 7, d = id & 127;
    float run = 0.f;
    for (int ch = 0; ch < NCH; ch++) {
        int idx = (b*NCH + ch)*DD + d;
        float v = g_csum[idx];
        g_csum[idx] = run;
        run += v;
    }
}

// ---------------- K3c: finalize prefix -> bf16 hi/lo ----------------
__global__ void k_prefix(const float* __restrict__ x) {
    int ch = blockIdx.x, b = blockIdx.y, d = threadIdx.x;
    __shared__ float es[BSB], rs[BSB];
    size_t base = (size_t)b * LTOK + (size_t)ch * BSB;
    for (int t = d; t < BSB; t += DD) { es[t] = g_e[base + t]; rs[t] = g_r[base + t]; }
    __syncthreads();
    float run = g_csum[(b*NCH + ch)*DD + d];
    const float* xp = x + base * DD + d;
    __nv_bfloat16* ph = g_ph + base * DD + d;
    __nv_bfloat16* pl = g_pl + base * DD + d;
    #pragma unroll 4
    for (int t = 0; t < BSB; t++) {
        float xv = xp[(size_t)t*DD];
        run += es[t] * xv;
        float pv = run * rs[t] + xv;
        __nv_bfloat16 h = __float2bfloat16(pv);
        ph[(size_t)t*DD] = h;
        pl[(size_t)t*DD] = __float2bfloat16(pv - __bfloat162float(h));
    }
}

// ---------------- K4: conv1d via ldmatrix + mma.sync bf16 (hi/lo 3-pass) ----------
// CTA: 256 positions x 128 out. 16 warps, each 32 pos x 64 out.
// A smem: 261 rows (pos-2 .. pos+258) x 128 in-ch, hi+lo planes, pitch 272B.
// W smem: per shift k, 128 out x 128 in, hi+lo planes.
// B fragment: W stored [n][k] with k contiguous -> NON-trans ldmatrix yields the
// .col B fragment (reg = 2 consecutive k for fixed n) directly.
#define PITCH 272
#define OFF_AH 0
#define OFF_AL 70992            // 261*272
#define OFF_WH 141984
#define OFF_WL 176800           // +128*272
#define CONV_SMEM 211616
__global__ __launch_bounds__(512, 1) void k_conv(const float* __restrict__ cb) {
    extern __shared__ char sm[];
    int tid = threadIdx.x, lane = tid & 31, wid = tid >> 5;
    int wm = wid >> 1, wn = wid & 1;
    int nb = blockIdx.x >> 1;              // conv block 0..511
    int p0loc = (blockIdx.x & 1) << 8;     // 0 or 256
    uint32_t sb = smem_u32(sm);
    int lr = lane & 15, lh = lane >> 4;

    // stage A (hi + lo)
    for (int t = tid; t < 261*16; t += 512) {
        int r = t >> 4, c = (t & 15) << 3;
        int q = p0loc + r - 2;
        uint4 vh = make_uint4(0,0,0,0), vl = make_uint4(0,0,0,0);
        if (q >= 0 && q < 512) {
            size_t g = (((size_t)nb*512 + q) << 7) + c;
            vh = *(const uint4*)(const void*)(g_ph + g);
            vl = *(const uint4*)(const void*)(g_pl + g);
        }
        *(uint4*)(sm + OFF_AH + r*PITCH + c*2) = vh;
        *(uint4*)(sm + OFF_AL + r*PITCH + c*2) = vl;
    }

    float c[2][8][4];
    #pragma unroll
    for (int mt = 0; mt < 2; mt++)
        #pragma unroll
        for (int nt = 0; nt < 8; nt++)
            #pragma unroll
            for (int v = 0; v < 4; v++) c[mt][nt][v] = 0.f;

    for (int k = 0; k < KW; k++) {
        __syncthreads();
        for (int t = tid; t < 128*16; t += 512) {
            int o = t >> 4, cc = (t & 15) << 3;
            size_t g = (((size_t)k*128 + o) << 7) + cc;
            *(uint4*)(sm + OFF_WH + o*PITCH + cc*2) = *(const uint4*)(const void*)(g_wh + g);
            *(uint4*)(sm + OFF_WL + o*PITCH + cc*2) = *(const uint4*)(const void*)(g_wl + g);
        }
        __syncthreads();
        #pragma unroll
        for (int pass = 0; pass < 3; pass++) {
            uint32_t abase = sb + (pass == 2 ? OFF_AL : OFF_AH)
                           + (wm*32 + k + lr)*PITCH + lh*16;
            uint32_t bbase = sb + (pass == 1 ? OFF_WL : OFF_WH)
                           + (wn*64 + lr)*PITCH + lh*16;
            #pragma unroll
            for (int kc = 0; kc < 8; kc++) {
                uint32_t a[2][4];
                ldsm_x4(a[0], abase + kc*32);
                ldsm_x4(a[1], abase + kc*32 + 16*PITCH);
                #pragma unroll
                for (int ntp = 0; ntp < 4; ntp++) {
                    uint32_t bf[4];
                    ldsm_x4(bf, bbase + ntp*16*PITCH + kc*32);
                    #pragma unroll
                    for (int mt = 0; mt < 2; mt++) {
                        mma16816(c[mt][2*ntp],     a[mt], bf[0], bf[2]);
                        mma16816(c[mt][2*ntp + 1], a[mt], bf[1], bf[3]);
                    }
                }
            }
        }
    }

    // epilogue: bias, store, fused per-block channel max
    int pbase = nb*512 + p0loc + wm*32 + (lane >> 2);
    #pragma unroll
    for (int nt = 0; nt < 8; nt++) {
        int col = wn*64 + nt*8 + (lane & 3)*2;
        float2 b2 = *(const float2*)(cb + col);
        float mx = -INFINITY, my = -INFINITY;
        #pragma unroll
        for (int mt = 0; mt < 2; mt++) {
            float x0 = c[mt][nt][0] + b2.x, y0 = c[mt][nt][1] + b2.y;
            float x1 = c[mt][nt][2] + b2.x, y1 = c[mt][nt][3] + b2.y;
            int row = pbase + mt*16;
            *(float2*)(g_conv + ((size_t)row << 7) + col)       = make_float2(x0, y0);
            *(float2*)(g_conv + ((size_t)(row + 8) << 7) + col) = make_float2(x1, y1);
            mx = fmaxf(mx, fmaxf(x0, x1));
            my = fmaxf(my, fmaxf(y0, y1));
        }
        #pragma unroll
        for (int o = 4; o < 32; o <<= 1) {
            mx = fmaxf(mx, __shfl_xor_sync(~0u, mx, o));
            my = fmaxf(my, __shfl_xor_sync(~0u, my, o));
        }
        if (lane < 4) {
            int cg = wn*64 + nt*8 + lane*2;
            atomicMax(&g_repr[nb*DD + cg],     enc_f(mx));
            atomicMax(&g_repr[nb*DD + cg + 1], enc_f(my));
        }
    }
}

// ---------------- K6: a_s = attn(block_repr, blocks_c, blocks_c) ----------------
__global__ void k_attn_s() {
    int n = blockIdx.x, tid = threadIdx.x;
    int lane = tid & 31, w = tid >> 5;
    __shared__ float s[BSB];
    __shared__ float red[128];
    float4 q4;
    q4.x = dec_f(g_repr[n*DD + lane*4 + 0]);
    q4.y = dec_f(g_repr[n*DD + lane*4 + 1]);
    q4.z = dec_f(g_repr[n*DD + lane*4 + 2]);
    q4.w = dec_f(g_repr[n*DD + lane*4 + 3]);
    const float* kv = g_conv + (size_t)n * BSB * DD;
    for (int j = w; j < BSB; j += 4) {
        float4 k4 = *(const float4*)&kv[(size_t)j*DD + lane*4];
        float p = q4.x*k4.x + q4.y*k4.y + q4.z*k4.z + q4.w*k4.w;
        #pragma unroll
        for (int o = 16; o; o >>= 1) p += __shfl_xor_sync(~0u, p, o);
        if (lane == 0) s[j] = p * SCALEF;
    }
    __syncthreads();
    float mx = -INFINITY;
    for (int j = tid; j < BSB; j += 128) mx = fmaxf(mx, s[j]);
    red[tid] = mx; __syncthreads();
    for (int st = 64; st; st >>= 1) { if (tid < st) red[tid] = fmaxf(red[tid], red[tid+st]); __syncthreads(); }
    float M = red[0]; __syncthreads();
    float sm = 0.f;
    for (int j = tid; j < BSB; j += 128) { float e = expf(s[j] - M); s[j] = e; sm += e; }
    red[tid] = sm; __syncthreads();
    for (int st = 64; st; st >>= 1) { if (tid < st) red[tid] += red[tid+st]; __syncthreads(); }
    float SUM = red[0]; __syncthreads();
    float acc = 0.f;
    #pragma unroll 4
    for (int j = 0; j < BSB; j++) acc += s[j] * kv[(size_t)j*DD + tid];
    g_as[n*DD + tid] = acc / SUM;
}

// ---------------- K7: a_o = attn(block_repr, xbo, xbo) ----------------
__global__ void k_attn_o() {
    int n = blockIdx.x, tid = threadIdx.x;
    int lane = tid & 31, w = tid >> 5;
    int bq = n >> 6, c = n & 63;
    __shared__ float s[128];
    __shared__ float red[128];
    float qa[4];
    #pragma unroll
    for (int q = 0; q < 4; q++) qa[q] = dec_f(g_repr[n*DD + lane*4 + q]);
    for (int j = w; j < 128; j += 4) {
        int tt = 448 + c*BSB + j; if (tt > LTOK-1) tt = LTOK-1;
        size_t ro = ((size_t)bq*LTOK + tt) << 7;
        float p = 0.f;
        #pragma unroll
        for (int q = 0; q < 4; q++) {
            int chn = lane*4 + q;
            float kvv = __bfloat162float(g_ph[ro + chn]) + __bfloat162float(g_pl[ro + chn]);
            p += qa[q] * kvv;
        }
        #pragma unroll
        for (int o = 16; o; o >>= 1) p += __shfl_xor_sync(~0u, p, o);
        if (lane == 0) s[j] = p * SCALEF;
    }
    __syncthreads();
    red[tid] = s[tid]; __syncthreads();
    for (int st = 64; st; st >>= 1) { if (tid < st) red[tid] = fmaxf(red[tid], red[tid+st]); __syncthreads(); }
    float M = red[0]; __syncthreads();
    float e = expf(s[tid] - M); s[tid] = e;
    red[tid] = e; __syncthreads();
    for (int st = 64; st; st >>= 1) { if (tid < st) red[tid] += red[tid+st]; __syncthreads(); }
    float SUM = red[0]; __syncthreads();
    float acc = 0.f;
    for (int j = 0; j < 128; j++) {
        int tt = 448 + c*BSB + j; if (tt > LTOK-1) tt = LTOK-1;
        size_t ro = ((size_t)bq*LTOK + tt) << 7;
        acc += s[j] * (__bfloat162float(g_ph[ro + tid]) + __bfloat162float(g_pl[ro + tid]));
    }
    g_ao[n*DD + tid] = acc / SUM;
}

// ---------------- K8: fusion GEMV ----------------
__global__ void k_fuse(const float* __restrict__ fw, const float* __restrict__ fb,
                       float* __restrict__ out, int out_size) {
    int n = blockIdx.x, o = threadIdx.x;
    __shared__ float f[384];
    f[o]       = g_as[n*DD + o];
    f[128 + o] = g_ao[n*DD + o];
    f[256 + o] = dec_f(g_repr[n*DD + o]);
    __syncthreads();
    float acc = fb[o];
    #pragma unroll 4
    for (int i = 0; i < 384; i++) acc += f[i] * fw[i*DD + o];
    for (int off = 0; off + NBL*DD <= out_size; off += NBL*DD)
        out[off + n*DD + o] = acc;
}

// ---------------- launch ----------------
extern "C" void kernel_launch(void* const* d_in, const int* in_sizes, int n_in,
                              void* d_out, int out_size) {
    const float* x        = (const float*)d_in[0];
    const float* w_lw     = (const float*)d_in[1];
    const float* b_lw     = (const float*)d_in[2];
    const float* conv_w   = (const float*)d_in[3];
    const float* conv_b   = (const float*)d_in[4];
    const float* fusion_w = (const float*)d_in[5];
    const float* fusion_b = (const float*)d_in[6];
    float* out = (float*)d_out;

    cudaFuncSetAttribute(k_conv, cudaFuncAttributeMaxDynamicSharedMemorySize, CONV_SMEM);

    k_wt<<<96, 1024>>>(conv_w);
    k_init_repr<<<64, 1024>>>();
    k_logits<<<BB*LTOK/8, 256>>>(x, w_lw, b_lw);
    k_cmax<<<dim3(NCH, BB), 256>>>();
    k_cmaxscan<<<1, 8>>>();
    k_escan<<<dim3(NCH, BB), 512>>>();
    k_csscan<<<1, 8>>>();
    k_rfin<<<dim3(NCH, BB), 512>>>();
    k_chunksum<<<dim3(NCH, BB), 128>>>(x);
    k_chscan<<<1, 1024>>>();
    k_prefix<<<dim3(NCH, BB), 128>>>(x);
    k_conv<<<1024, 512, CONV_SMEM>>>(conv_b);
    k_attn_s<<<NBL, 128>>>();
    k_attn_o<<<NBL, 128>>>();
    k_fuse<<<NBL, 128>>>(fusion_w, fusion_b, out, out_size);
}

// round 6
// speedup vs baseline: 2.0038x; 1.2542x over previous
#include <cuda_runtime.h>
#include <cuda_bf16.h>
#include <math.h>
#include <stdint.h>

#define BB   8
#define LTOK 32768
#define DD   128
#define BSB  512
#define NBL  512
#define KW   6
#define NCH  64
#define SCALEF 0.08838834764831845f

// ---------------- device scratch ----------------
__device__ float    g_logits[BB*LTOK];
__device__ float    g_e[BB*LTOK];
__device__ float    g_r[BB*LTOK];
__device__ float    g_cm[BB*NCH];
__device__ float    g_cm0[BB*NCH];
__device__ float    g_cs[BB*NCH];
__device__ float    g_cp0[BB*NCH];
__device__ float    g_csum[BB*NCH*DD];
__device__ __align__(16) __nv_bfloat16 g_ph[(size_t)BB*LTOK*DD];   // prefix hi
__device__ __align__(16) __nv_bfloat16 g_pl[(size_t)BB*LTOK*DD];   // prefix lo
__device__ float    g_conv[(size_t)NBL*BSB*DD];
__device__ unsigned g_repr[NBL*DD];
__device__ float    g_as[NBL*DD];
__device__ float    g_ao[NBL*DD];
__device__ __align__(16) __nv_bfloat16 g_wh[KW*DD*DD];  // [k][o][i]
__device__ __align__(16) __nv_bfloat16 g_wl[KW*DD*DD];

// ---------------- helpers ----------------
__device__ __forceinline__ unsigned enc_f(float f) {
    unsigned u = __float_as_uint(f);
    return (u & 0x80000000u) ? ~u : (u | 0x80000000u);
}
__device__ __forceinline__ float dec_f(unsigned u) {
    u = (u & 0x80000000u) ? (u & 0x7fffffffu) : ~u;
    return __uint_as_float(u);
}
__device__ __forceinline__ uint32_t smem_u32(const void* p) {
    uint32_t a;
    asm("{ .reg .u64 t; cvta.to.shared.u64 t, %1; cvt.u32.u64 %0, t; }" : "=r"(a) : "l"(p));
    return a;
}
__device__ __forceinline__ void ldsm_x4(uint32_t* r, uint32_t addr) {
    asm volatile("ldmatrix.sync.aligned.m8n8.x4.shared.b16 {%0,%1,%2,%3}, [%4];"
        : "=r"(r[0]), "=r"(r[1]), "=r"(r[2]), "=r"(r[3]) : "r"(addr));
}
__device__ __forceinline__ void mma16816(float* c, const uint32_t* a, uint32_t b0, uint32_t b1) {
    asm volatile(
        "mma.sync.aligned.m16n8k16.row.col.f32.bf16.bf16.f32 "
        "{%0,%1,%2,%3}, {%4,%5,%6,%7}, {%8,%9}, {%0,%1,%2,%3};"
        : "+f"(c[0]), "+f"(c[1]), "+f"(c[2]), "+f"(c[3])
        : "r"(a[0]), "r"(a[1]), "r"(a[2]), "r"(a[3]), "r"(b0), "r"(b1));
}
__device__ __forceinline__ void cpa16(uint32_t dst, const void* src) {
    asm volatile("cp.async.cg.shared.global [%0], [%1], 16;" :: "r"(dst), "l"(src) : "memory");
}
__device__ __forceinline__ void cpa16z(uint32_t dst, const void* src, int srcsize) {
    asm volatile("cp.async.cg.shared.global [%0], [%1], 16, %2;" :: "r"(dst), "l"(src), "r"(srcsize) : "memory");
}
#define CPA_COMMIT() asm volatile("cp.async.commit_group;" ::: "memory")
#define CPA_WAIT(n)  asm volatile("cp.async.wait_group %0;" :: "n"(n) : "memory")

// ---------------- K0: split conv weights to bf16 hi/lo [k][o][i] ----------------
__global__ void k_wt(const float* __restrict__ cw) {
    int idx = blockIdx.x * blockDim.x + threadIdx.x;
    if (idx < KW*DD*DD) {
        int i = idx & 127;
        int r = idx >> 7;
        int o = r & 127;
        int kk = r >> 7;
        float v = cw[o*768 + i*6 + kk];
        __nv_bfloat16 h = __float2bfloat16(v);
        g_wh[idx] = h;
        g_wl[idx] = __float2bfloat16(v - __bfloat162float(h));
    }
}

__global__ void k_init_repr() {
    int i = blockIdx.x * blockDim.x + threadIdx.x;
    if (i < NBL*DD) g_repr[i] = 0u;
}

// ---------------- K1: logits = silu(x @ w + b) ----------------
__global__ void k_logits(const float* __restrict__ x, const float* __restrict__ w,
                         const float* __restrict__ bl) {
    int gw = blockIdx.x * (blockDim.x >> 5) + (threadIdx.x >> 5);
    int lane = threadIdx.x & 31;
    if (gw >= BB*LTOK) return;
    float4 xv = *(const float4*)&x[(size_t)gw*DD + lane*4];
    float4 wv = *(const float4*)&w[lane*4];
    float s = xv.x*wv.x + xv.y*wv.y + xv.z*wv.z + xv.w*wv.w;
    #pragma unroll
    for (int o = 16; o; o >>= 1) s += __shfl_xor_sync(~0u, s, o);
    if (lane == 0) {
        float z = s + bl[0];
        g_logits[gw] = z / (1.f + expf(-z));
    }
}

// ---------------- parallel scan (chunked) ----------------
template<bool MX>
__device__ __forceinline__ float iscan512(float v, float* ws) {
    int lane = threadIdx.x & 31, w = threadIdx.x >> 5;
    float x = v;
    #pragma unroll
    for (int o = 1; o < 32; o <<= 1) {
        float y = __shfl_up_sync(~0u, x, o);
        if (lane >= o) x = MX ? fmaxf(x, y) : (x + y);
    }
    if (lane == 31) ws[w] = x;
    __syncthreads();
    if (w == 0 && lane < 16) {
        float t = ws[lane];
        #pragma unroll
        for (int o = 1; o < 16; o <<= 1) {
            float y = __shfl_up_sync(0xFFFFu, t, o);
            if (lane >= o) t = MX ? fmaxf(t, y) : (t + y);
        }
        ws[lane] = t;
    }
    __syncthreads();
    if (w > 0) {
        float pre = ws[w-1];
        x = MX ? fmaxf(x, pre) : (x + pre);
    }
    return x;
}

__global__ void k_cmax() {
    __shared__ float red[256];
    int c = blockIdx.x, b = blockIdx.y, t = threadIdx.x;
    int base = b*LTOK + c*BSB;
    float v = fmaxf(g_logits[base + t], g_logits[base + t + 256]);
    red[t] = v; __syncthreads();
    for (int st = 128; st; st >>= 1) { if (t < st) red[t] = fmaxf(red[t], red[t+st]); __syncthreads(); }
    if (t == 0) g_cm[b*NCH + c] = red[0];
}
__global__ void k_cmaxscan() {
    int b = threadIdx.x; if (b >= BB) return;
    float run = -INFINITY;
    for (int c = 0; c < NCH; c++) {
        g_cm0[b*NCH + c] = run;
        run = fmaxf(run, g_cm[b*NCH + c]);
    }
}
__global__ __launch_bounds__(512) void k_escan() {
    __shared__ float ws[16];
    int c = blockIdx.x, b = blockIdx.y, t = threadIdx.x;
    int base = b*LTOK + c*BSB;
    float l = g_logits[base + t];
    float lm = iscan512<true>(l, ws);
    float M = fmaxf(lm, g_cm0[b*NCH + c]);
    float e = expf(l - M);
    g_e[base + t] = e;
    __syncthreads();
    float S = iscan512<false>(e, ws);
    if (t == 511) g_cs[b*NCH + c] = S;
}
__global__ void k_csscan() {
    int b = threadIdx.x; if (b >= BB) return;
    float run = 0.f;
    for (int c = 0; c < NCH; c++) {
        g_cp0[b*NCH + c] = run;
        run += g_cs[b*NCH + c];
    }
}
__global__ __launch_bounds__(512) void k_rfin() {
    __shared__ float ws[16];
    int c = blockIdx.x, b = blockIdx.y, t = threadIdx.x;
    int base = b*LTOK + c*BSB;
    float e = g_e[base + t];
    float P = iscan512<false>(e, ws) + g_cp0[b*NCH + c];
    g_r[base + t] = 1.f / P;
}

// ---------------- K3a: chunk partial sums of e*x ----------------
__global__ void k_chunksum(const float* __restrict__ x) {
    int ch = blockIdx.x, b = blockIdx.y, d = threadIdx.x;
    __shared__ float es[BSB];
    size_t base = (size_t)b * LTOK + (size_t)ch * BSB;
    for (int t = d; t < BSB; t += DD) es[t] = g_e[base + t];
    __syncthreads();
    const float* xp = x + base * DD + d;
    float a0 = 0, a1 = 0, a2 = 0, a3 = 0;
    for (int t = 0; t < BSB; t += 4) {
        a0 += es[t+0] * xp[(size_t)(t+0)*DD];
        a1 += es[t+1] * xp[(size_t)(t+1)*DD];
        a2 += es[t+2] * xp[(size_t)(t+2)*DD];
        a3 += es[t+3] * xp[(size_t)(t+3)*DD];
    }
    g_csum[(b*NCH + ch)*DD + d] = (a0 + a1) + (a2 + a3);
}

__global__ void k_chscan() {
    int id = threadIdx.x;            // 1024 = 8*128
    int b = id >> 7, d = id & 127;
    float run = 0.f;
    for (int ch = 0; ch < NCH; ch++) {
        int idx = (b*NCH + ch)*DD + d;
        float v = g_csum[idx];
        g_csum[idx] = run;
        run += v;
    }
}

// ---------------- K3c: finalize prefix -> bf16 hi/lo ----------------
__global__ void k_prefix(const float* __restrict__ x) {
    int ch = blockIdx.x, b = blockIdx.y, d = threadIdx.x;
    __shared__ float es[BSB], rs[BSB];
    size_t base = (size_t)b * LTOK + (size_t)ch * BSB;
    for (int t = d; t < BSB; t += DD) { es[t] = g_e[base + t]; rs[t] = g_r[base + t]; }
    __syncthreads();
    float run = g_csum[(b*NCH + ch)*DD + d];
    const float* xp = x + base * DD + d;
    __nv_bfloat16* ph = g_ph + base * DD + d;
    __nv_bfloat16* pl = g_pl + base * DD + d;
    #pragma unroll 4
    for (int t = 0; t < BSB; t++) {
        float xv = xp[(size_t)t*DD];
        run += es[t] * xv;
        float pv = run * rs[t] + xv;
        __nv_bfloat16 h = __float2bfloat16(pv);
        ph[(size_t)t*DD] = h;
        pl[(size_t)t*DD] = __float2bfloat16(pv - __bfloat162float(h));
    }
}

// ---------------- K4: conv1d via mma.sync bf16, cp.async pipelined ----------
// CTA: 256 positions x 128 out. 16 warps, each 32 pos x 64 out.
// Phase 0: A = hi plane resident; stages (k,whi),(k,wlo) for k=0..5  (12 stages)
// Phase 1: A = lo plane resident; stages (k,whi) for k=0..5          (6 stages)
// W triple-buffered 128x128 bf16 stages loaded with cp.async.cg.
#define PITCH 272
#define A_OFF 0                 // 261*272 = 70992
#define W_OFF 71040
#define WSZ   34816             // 128*272
#define CONV_SMEM (W_OFF + 3*WSZ)   // 175488
__device__ __forceinline__ void conv_issueW(int k, int pl, uint32_t dstbase, int tid) {
    const __nv_bfloat16* wsrc = pl ? g_wl : g_wh;
    #pragma unroll
    for (int u = 0; u < 4; u++) {
        int t = tid + u*512;
        int o = t >> 4, cc = (t & 15) << 3;
        cpa16(dstbase + o*PITCH + cc*2, wsrc + (((size_t)(k*128 + o)) << 7) + cc);
    }
}
__global__ __launch_bounds__(512, 1) void k_conv(const float* __restrict__ cb) {
    extern __shared__ char sm[];
    uint32_t sb = smem_u32(sm);
    int tid = threadIdx.x, lane = tid & 31, wid = tid >> 5;
    int wm = wid >> 1, wn = wid & 1;
    int nb = blockIdx.x >> 1;
    int p0loc = (blockIdx.x & 1) << 8;
    int lr = lane & 15, lh = lane >> 4;

    float c[2][8][4];
    #pragma unroll
    for (int mt = 0; mt < 2; mt++)
        #pragma unroll
        for (int nt = 0; nt < 8; nt++)
            #pragma unroll
            for (int v = 0; v < 4; v++) c[mt][nt][v] = 0.f;

    for (int ph = 0; ph < 2; ph++) {
        const __nv_bfloat16* asrc = ph ? g_pl : g_ph;
        // stage A plane (group 0 of this phase)
        for (int t = tid; t < 261*16; t += 512) {
            int r = t >> 4, cc = (t & 15) << 3;
            int q = p0loc + r - 2;
            const void* src = asrc;
            int sz = 0;
            if (q >= 0 && q < 512) {
                src = asrc + ((((size_t)nb << 9) + q) << 7) + cc;
                sz = 16;
            }
            cpa16z(sb + A_OFF + r*PITCH + cc*2, src, sz);
        }
        CPA_COMMIT();
        const int nst = ph ? 6 : 12;
        // prologue: first 3 W stages
        #pragma unroll
        for (int s = 0; s < 3; s++) {
            int k = ph ? s : (s >> 1), pl = ph ? 0 : (s & 1);
            conv_issueW(k, pl, sb + W_OFF + s*WSZ, tid);
            CPA_COMMIT();
        }
        CPA_WAIT(2);              // A + W stage0 complete
        __syncthreads();
        for (int s = 0; s < nst; s++) {
            int k = ph ? s : (s >> 1);
            uint32_t abase = sb + A_OFF + (wm*32 + k + lr)*PITCH + lh*16;
            uint32_t bbase = sb + W_OFF + (s % 3)*WSZ + (wn*64 + lr)*PITCH + lh*16;
            #pragma unroll
            for (int kc = 0; kc < 8; kc++) {
                uint32_t a[2][4];
                ldsm_x4(a[0], abase + kc*32);
                ldsm_x4(a[1], abase + kc*32 + 16*PITCH);
                #pragma unroll
                for (int ntp = 0; ntp < 4; ntp++) {
                    uint32_t bf[4];
                    ldsm_x4(bf, bbase + ntp*16*PITCH + kc*32);
                    #pragma unroll
                    for (int mt = 0; mt < 2; mt++) {
                        mma16816(c[mt][2*ntp],     a[mt], bf[0], bf[2]);
                        mma16816(c[mt][2*ntp + 1], a[mt], bf[1], bf[3]);
                    }
                }
            }
            __syncthreads();       // everyone done with buffer s%3
            if (s + 3 < nst) {
                int k2 = ph ? (s+3) : ((s+3) >> 1), pl2 = ph ? 0 : ((s+3) & 1);
                conv_issueW(k2, pl2, sb + W_OFF + ((s+3) % 3)*WSZ, tid);
                CPA_COMMIT();
            }
            if (s + 1 < nst) {
                CPA_WAIT(2);       // stage s+1 complete
                __syncthreads();
            }
        }
        CPA_WAIT(0);
        __syncthreads();
    }

    // epilogue: bias, store, fused per-block channel max
    int pbase = nb*512 + p0loc + wm*32 + (lane >> 2);
    #pragma unroll
    for (int nt = 0; nt < 8; nt++) {
        int col = wn*64 + nt*8 + (lane & 3)*2;
        float2 b2 = *(const float2*)(cb + col);
        float mx = -INFINITY, my = -INFINITY;
        #pragma unroll
        for (int mt = 0; mt < 2; mt++) {
            float x0 = c[mt][nt][0] + b2.x, y0 = c[mt][nt][1] + b2.y;
            float x1 = c[mt][nt][2] + b2.x, y1 = c[mt][nt][3] + b2.y;
            int row = pbase + mt*16;
            *(float2*)(g_conv + ((size_t)row << 7) + col)       = make_float2(x0, y0);
            *(float2*)(g_conv + ((size_t)(row + 8) << 7) + col) = make_float2(x1, y1);
            mx = fmaxf(mx, fmaxf(x0, x1));
            my = fmaxf(my, fmaxf(y0, y1));
        }
        #pragma unroll
        for (int o = 4; o < 32; o <<= 1) {
            mx = fmaxf(mx, __shfl_xor_sync(~0u, mx, o));
            my = fmaxf(my, __shfl_xor_sync(~0u, my, o));
        }
        if (lane < 4) {
            int cg = wn*64 + nt*8 + lane*2;
            atomicMax(&g_repr[nb*DD + cg],     enc_f(mx));
            atomicMax(&g_repr[nb*DD + cg + 1], enc_f(my));
        }
    }
}

// ---------------- K6: a_s = attn(block_repr, blocks_c, blocks_c) ----------------
__global__ void k_attn_s() {
    int n = blockIdx.x, tid = threadIdx.x;
    int lane = tid & 31, w = tid >> 5;
    __shared__ float s[BSB];
    __shared__ float red[128];
    float4 q4;
    q4.x = dec_f(g_repr[n*DD + lane*4 + 0]);
    q4.y = dec_f(g_repr[n*DD + lane*4 + 1]);
    q4.z = dec_f(g_repr[n*DD + lane*4 + 2]);
    q4.w = dec_f(g_repr[n*DD + lane*4 + 3]);
    const float* kv = g_conv + (size_t)n * BSB * DD;
    for (int j = w; j < BSB; j += 4) {
        float4 k4 = *(const float4*)&kv[(size_t)j*DD + lane*4];
        float p = q4.x*k4.x + q4.y*k4.y + q4.z*k4.z + q4.w*k4.w;
        #pragma unroll
        for (int o = 16; o; o >>= 1) p += __shfl_xor_sync(~0u, p, o);
        if (lane == 0) s[j] = p * SCALEF;
    }
    __syncthreads();
    float mx = -INFINITY;
    for (int j = tid; j < BSB; j += 128) mx = fmaxf(mx, s[j]);
    red[tid] = mx; __syncthreads();
    for (int st = 64; st; st >>= 1) { if (tid < st) red[tid] = fmaxf(red[tid], red[tid+st]); __syncthreads(); }
    float M = red[0]; __syncthreads();
    float sm = 0.f;
    for (int j = tid; j < BSB; j += 128) { float e = expf(s[j] - M); s[j] = e; sm += e; }
    red[tid] = sm; __syncthreads();
    for (int st = 64; st; st >>= 1) { if (tid < st) red[tid] += red[tid+st]; __syncthreads(); }
    float SUM = red[0]; __syncthreads();
    float acc = 0.f;
    #pragma unroll 4
    for (int j = 0; j < BSB; j++) acc += s[j] * kv[(size_t)j*DD + tid];
    g_as[n*DD + tid] = acc / SUM;
}

// ---------------- K7: a_o = attn(block_repr, xbo, xbo) ----------------
__global__ void k_attn_o() {
    int n = blockIdx.x, tid = threadIdx.x;
    int lane = tid & 31, w = tid >> 5;
    int bq = n >> 6, c = n & 63;
    __shared__ float s[128];
    __shared__ float red[128];
    float qa[4];
    #pragma unroll
    for (int q = 0; q < 4; q++) qa[q] = dec_f(g_repr[n*DD + lane*4 + q]);
    for (int j = w; j < 128; j += 4) {
        int tt = 448 + c*BSB + j; if (tt > LTOK-1) tt = LTOK-1;
        size_t ro = ((size_t)bq*LTOK + tt) << 7;
        float p = 0.f;
        #pragma unroll
        for (int q = 0; q < 4; q++) {
            int chn = lane*4 + q;
            float kvv = __bfloat162float(g_ph[ro + chn]) + __bfloat162float(g_pl[ro + chn]);
            p += qa[q] * kvv;
        }
        #pragma unroll
        for (int o = 16; o; o >>= 1) p += __shfl_xor_sync(~0u, p, o);
        if (lane == 0) s[j] = p * SCALEF;
    }
    __syncthreads();
    red[tid] = s[tid]; __syncthreads();
    for (int st = 64; st; st >>= 1) { if (tid < st) red[tid] = fmaxf(red[tid], red[tid+st]); __syncthreads(); }
    float M = red[0]; __syncthreads();
    float e = expf(s[tid] - M); s[tid] = e;
    red[tid] = e; __syncthreads();
    for (int st = 64; st; st >>= 1) { if (tid < st) red[tid] += red[tid+st]; __syncthreads(); }
    float SUM = red[0]; __syncthreads();
    float acc = 0.f;
    for (int j = 0; j < 128; j++) {
        int tt = 448 + c*BSB + j; if (tt > LTOK-1) tt = LTOK-1;
        size_t ro = ((size_t)bq*LTOK + tt) << 7;
        acc += s[j] * (__bfloat162float(g_ph[ro + tid]) + __bfloat162float(g_pl[ro + tid]));
    }
    g_ao[n*DD + tid] = acc / SUM;
}

// ---------------- K8: fusion GEMV ----------------
__global__ void k_fuse(const float* __restrict__ fw, const float* __restrict__ fb,
                       float* __restrict__ out, int out_size) {
    int n = blockIdx.x, o = threadIdx.x;
    __shared__ float f[384];
    f[o]       = g_as[n*DD + o];
    f[128 + o] = g_ao[n*DD + o];
    f[256 + o] = dec_f(g_repr[n*DD + o]);
    __syncthreads();
    float acc = fb[o];
    #pragma unroll 4
    for (int i = 0; i < 384; i++) acc += f[i] * fw[i*DD + o];
    for (int off = 0; off + NBL*DD <= out_size; off += NBL*DD)
        out[off + n*DD + o] = acc;
}

// ---------------- launch ----------------
extern "C" void kernel_launch(void* const* d_in, const int* in_sizes, int n_in,
                              void* d_out, int out_size) {
    const float* x        = (const float*)d_in[0];
    const float* w_lw     = (const float*)d_in[1];
    const float* b_lw     = (const float*)d_in[2];
    const float* conv_w   = (const float*)d_in[3];
    const float* conv_b   = (const float*)d_in[4];
    const float* fusion_w = (const float*)d_in[5];
    const float* fusion_b = (const float*)d_in[6];
    float* out = (float*)d_out;

    cudaFuncSetAttribute(k_conv, cudaFuncAttributeMaxDynamicSharedMemorySize, CONV_SMEM);

    k_wt<<<96, 1024>>>(conv_w);
    k_init_repr<<<64, 1024>>>();
    k_logits<<<BB*LTOK/8, 256>>>(x, w_lw, b_lw);
    k_cmax<<<dim3(NCH, BB), 256>>>();
    k_cmaxscan<<<1, 8>>>();
    k_escan<<<dim3(NCH, BB), 512>>>();
    k_csscan<<<1, 8>>>();
    k_rfin<<<dim3(NCH, BB), 512>>>();
    k_chunksum<<<dim3(NCH, BB), 128>>>(x);
    k_chscan<<<1, 1024>>>();
    k_prefix<<<dim3(NCH, BB), 128>>>(x);
    k_conv<<<1024, 512, CONV_SMEM>>>(conv_b);
    k_attn_s<<<NBL, 128>>>();
    k_attn_o<<<NBL, 128>>>();
    k_fuse<<<NBL, 128>>>(fusion_w, fusion_b, out, out_size);
}

// round 7
// speedup vs baseline: 2.3924x; 1.1940x over previous
#include <cuda_runtime.h>
#include <cuda_fp16.h>
#include <math.h>
#include <stdint.h>

#define BB   8
#define LTOK 32768
#define DD   128
#define BSB  512
#define NBL  512
#define KW   6
#define NCH  64
#define SCALEF 0.08838834764831845f

// ---------------- device scratch ----------------
__device__ float    g_logits[BB*LTOK];
__device__ float    g_e[BB*LTOK];
__device__ float    g_r[BB*LTOK];
__device__ float    g_cm[BB*NCH];
__device__ float    g_cm0[BB*NCH];
__device__ float    g_cs[BB*NCH];
__device__ float    g_cp0[BB*NCH];
__device__ float    g_csum[BB*NCH*DD];
__device__ __align__(16) __half g_ph[(size_t)BB*LTOK*DD];   // prefix hi (fp16)
__device__ __align__(16) __half g_pl[(size_t)BB*LTOK*DD];   // prefix lo (fp16)
__device__ float    g_conv[(size_t)NBL*BSB*DD];
__device__ unsigned g_repr[NBL*DD];
__device__ float    g_as[NBL*DD];
__device__ float    g_ao[NBL*DD];
__device__ __align__(16) __half g_wh[KW*DD*DD];  // [k][o][i], fp16

// ---------------- helpers ----------------
__device__ __forceinline__ unsigned enc_f(float f) {
    unsigned u = __float_as_uint(f);
    return (u & 0x80000000u) ? ~u : (u | 0x80000000u);
}
__device__ __forceinline__ float dec_f(unsigned u) {
    u = (u & 0x80000000u) ? (u & 0x7fffffffu) : ~u;
    return __uint_as_float(u);
}
__device__ __forceinline__ uint32_t smem_u32(const void* p) {
    uint32_t a;
    asm("{ .reg .u64 t; cvta.to.shared.u64 t, %1; cvt.u32.u64 %0, t; }" : "=r"(a) : "l"(p));
    return a;
}
__device__ __forceinline__ void ldsm_x4(uint32_t* r, uint32_t addr) {
    asm volatile("ldmatrix.sync.aligned.m8n8.x4.shared.b16 {%0,%1,%2,%3}, [%4];"
        : "=r"(r[0]), "=r"(r[1]), "=r"(r[2]), "=r"(r[3]) : "r"(addr));
}
__device__ __forceinline__ void mma16816(float* c, const uint32_t* a, uint32_t b0, uint32_t b1) {
    asm volatile(
        "mma.sync.aligned.m16n8k16.row.col.f32.f16.f16.f32 "
        "{%0,%1,%2,%3}, {%4,%5,%6,%7}, {%8,%9}, {%0,%1,%2,%3};"
        : "+f"(c[0]), "+f"(c[1]), "+f"(c[2]), "+f"(c[3])
        : "r"(a[0]), "r"(a[1]), "r"(a[2]), "r"(a[3]), "r"(b0), "r"(b1));
}
__device__ __forceinline__ void cpa16(uint32_t dst, const void* src) {
    asm volatile("cp.async.cg.shared.global [%0], [%1], 16;" :: "r"(dst), "l"(src) : "memory");
}
__device__ __forceinline__ void cpa16z(uint32_t dst, const void* src, int srcsize) {
    asm volatile("cp.async.cg.shared.global [%0], [%1], 16, %2;" :: "r"(dst), "l"(src), "r"(srcsize) : "memory");
}
#define CPA_COMMIT() asm volatile("cp.async.commit_group;" ::: "memory")
#define CPA_WAIT(n)  asm volatile("cp.async.wait_group %0;" :: "n"(n) : "memory")

// ---------------- K0: conv weights -> fp16 [k][o][i] ----------------
__global__ void k_wt(const float* __restrict__ cw) {
    int idx = blockIdx.x * blockDim.x + threadIdx.x;
    if (idx < KW*DD*DD) {
        int i = idx & 127;
        int r = idx >> 7;
        int o = r & 127;
        int kk = r >> 7;
        g_wh[idx] = __float2half(cw[o*768 + i*6 + kk]);
    }
}

__global__ void k_init_repr() {
    int i = blockIdx.x * blockDim.x + threadIdx.x;
    if (i < NBL*DD) g_repr[i] = 0u;
}

// ---------------- K1: logits = silu(x @ w + b) ----------------
__global__ void k_logits(const float* __restrict__ x, const float* __restrict__ w,
                         const float* __restrict__ bl) {
    int gw = blockIdx.x * (blockDim.x >> 5) + (threadIdx.x >> 5);
    int lane = threadIdx.x & 31;
    if (gw >= BB*LTOK) return;
    float4 xv = *(const float4*)&x[(size_t)gw*DD + lane*4];
    float4 wv = *(const float4*)&w[lane*4];
    float s = xv.x*wv.x + xv.y*wv.y + xv.z*wv.z + xv.w*wv.w;
    #pragma unroll
    for (int o = 16; o; o >>= 1) s += __shfl_xor_sync(~0u, s, o);
    if (lane == 0) {
        float z = s + bl[0];
        g_logits[gw] = z / (1.f + expf(-z));
    }
}

// ---------------- parallel scan (chunked) ----------------
template<bool MX>
__device__ __forceinline__ float iscan512(float v, float* ws) {
    int lane = threadIdx.x & 31, w = threadIdx.x >> 5;
    float x = v;
    #pragma unroll
    for (int o = 1; o < 32; o <<= 1) {
        float y = __shfl_up_sync(~0u, x, o);
        if (lane >= o) x = MX ? fmaxf(x, y) : (x + y);
    }
    if (lane == 31) ws[w] = x;
    __syncthreads();
    if (w == 0 && lane < 16) {
        float t = ws[lane];
        #pragma unroll
        for (int o = 1; o < 16; o <<= 1) {
            float y = __shfl_up_sync(0xFFFFu, t, o);
            if (lane >= o) t = MX ? fmaxf(t, y) : (t + y);
        }
        ws[lane] = t;
    }
    __syncthreads();
    if (w > 0) {
        float pre = ws[w-1];
        x = MX ? fmaxf(x, pre) : (x + pre);
    }
    return x;
}

__global__ void k_cmax() {
    __shared__ float red[256];
    int c = blockIdx.x, b = blockIdx.y, t = threadIdx.x;
    int base = b*LTOK + c*BSB;
    float v = fmaxf(g_logits[base + t], g_logits[base + t + 256]);
    red[t] = v; __syncthreads();
    for (int st = 128; st; st >>= 1) { if (t < st) red[t] = fmaxf(red[t], red[t+st]); __syncthreads(); }
    if (t == 0) g_cm[b*NCH + c] = red[0];
}
__global__ void k_cmaxscan() {
    int b = threadIdx.x; if (b >= BB) return;
    float run = -INFINITY;
    for (int c = 0; c < NCH; c++) {
        g_cm0[b*NCH + c] = run;
        run = fmaxf(run, g_cm[b*NCH + c]);
    }
}
__global__ __launch_bounds__(512) void k_escan() {
    __shared__ float ws[16];
    int c = blockIdx.x, b = blockIdx.y, t = threadIdx.x;
    int base = b*LTOK + c*BSB;
    float l = g_logits[base + t];
    float lm = iscan512<true>(l, ws);
    float M = fmaxf(lm, g_cm0[b*NCH + c]);
    float e = expf(l - M);
    g_e[base + t] = e;
    __syncthreads();
    float S = iscan512<false>(e, ws);
    if (t == 511) g_cs[b*NCH + c] = S;
}
__global__ void k_csscan() {
    int b = threadIdx.x; if (b >= BB) return;
    float run = 0.f;
    for (int c = 0; c < NCH; c++) {
        g_cp0[b*NCH + c] = run;
        run += g_cs[b*NCH + c];
    }
}
__global__ __launch_bounds__(512) void k_rfin() {
    __shared__ float ws[16];
    int c = blockIdx.x, b = blockIdx.y, t = threadIdx.x;
    int base = b*LTOK + c*BSB;
    float e = g_e[base + t];
    float P = iscan512<false>(e, ws) + g_cp0[b*NCH + c];
    g_r[base + t] = 1.f / P;
}

// ---------------- K3a: chunk partial sums of e*x ----------------
__global__ void k_chunksum(const float* __restrict__ x) {
    int ch = blockIdx.x, b = blockIdx.y, d = threadIdx.x;
    __shared__ float es[BSB];
    size_t base = (size_t)b * LTOK + (size_t)ch * BSB;
    for (int t = d; t < BSB; t += DD) es[t] = g_e[base + t];
    __syncthreads();
    const float* xp = x + base * DD + d;
    float a0 = 0, a1 = 0, a2 = 0, a3 = 0;
    for (int t = 0; t < BSB; t += 4) {
        a0 += es[t+0] * xp[(size_t)(t+0)*DD];
        a1 += es[t+1] * xp[(size_t)(t+1)*DD];
        a2 += es[t+2] * xp[(size_t)(t+2)*DD];
        a3 += es[t+3] * xp[(size_t)(t+3)*DD];
    }
    g_csum[(b*NCH + ch)*DD + d] = (a0 + a1) + (a2 + a3);
}

__global__ void k_chscan() {
    int id = threadIdx.x;            // 1024 = 8*128
    int b = id >> 7, d = id & 127;
    float run = 0.f;
    for (int ch = 0; ch < NCH; ch++) {
        int idx = (b*NCH + ch)*DD + d;
        float v = g_csum[idx];
        g_csum[idx] = run;
        run += v;
    }
}

// ---------------- K3c: finalize prefix -> fp16 hi/lo ----------------
__global__ void k_prefix(const float* __restrict__ x) {
    int ch = blockIdx.x, b = blockIdx.y, d = threadIdx.x;
    __shared__ float es[BSB], rs[BSB];
    size_t base = (size_t)b * LTOK + (size_t)ch * BSB;
    for (int t = d; t < BSB; t += DD) { es[t] = g_e[base + t]; rs[t] = g_r[base + t]; }
    __syncthreads();
    float run = g_csum[(b*NCH + ch)*DD + d];
    const float* xp = x + base * DD + d;
    __half* ph = g_ph + base * DD + d;
    __half* pl = g_pl + base * DD + d;
    #pragma unroll 4
    for (int t = 0; t < BSB; t++) {
        float xv = xp[(size_t)t*DD];
        run += es[t] * xv;
        float pv = run * rs[t] + xv;
        __half h = __float2half(pv);
        ph[(size_t)t*DD] = h;
        pl[(size_t)t*DD] = __float2half(pv - __half2float(h));
    }
}

// ---------------- K4: conv1d via mma.sync fp16 2-pass, cp.async pipelined ----------
// x = xh + xl exactly (fp16 pair); w ~ wh (fp16). conv = xh*wh + xl*wh (= x*wh).
// Phase 0: A = hi plane, 6 W stages (k=0..5). Phase 1: A = lo plane, 6 stages.
// W triple-buffered 128x128 fp16 stages loaded with cp.async.cg.
#define PITCH 272
#define A_OFF 0                 // 261*272 = 70992
#define W_OFF 71040
#define WSZ   34816             // 128*272
#define CONV_SMEM (W_OFF + 3*WSZ)   // 175488
__device__ __forceinline__ void conv_issueW(int k, uint32_t dstbase, int tid) {
    #pragma unroll
    for (int u = 0; u < 4; u++) {
        int t = tid + u*512;
        int o = t >> 4, cc = (t & 15) << 3;
        cpa16(dstbase + o*PITCH + cc*2, g_wh + (((size_t)(k*128 + o)) << 7) + cc);
    }
}
__global__ __launch_bounds__(512, 1) void k_conv(const float* __restrict__ cb) {
    extern __shared__ char sm[];
    uint32_t sb = smem_u32(sm);
    int tid = threadIdx.x, lane = tid & 31, wid = tid >> 5;
    int wm = wid >> 1, wn = wid & 1;
    int nb = blockIdx.x >> 1;
    int p0loc = (blockIdx.x & 1) << 8;
    int lr = lane & 15, lh = lane >> 4;

    float c[2][8][4];
    #pragma unroll
    for (int mt = 0; mt < 2; mt++)
        #pragma unroll
        for (int nt = 0; nt < 8; nt++)
            #pragma unroll
            for (int v = 0; v < 4; v++) c[mt][nt][v] = 0.f;

    for (int ph = 0; ph < 2; ph++) {
        const __half* asrc = ph ? g_pl : g_ph;
        // stage A plane
        for (int t = tid; t < 261*16; t += 512) {
            int r = t >> 4, cc = (t & 15) << 3;
            int q = p0loc + r - 2;
            const void* src = asrc;
            int sz = 0;
            if (q >= 0 && q < 512) {
                src = asrc + ((((size_t)nb << 9) + q) << 7) + cc;
                sz = 16;
            }
            cpa16z(sb + A_OFF + r*PITCH + cc*2, src, sz);
        }
        CPA_COMMIT();
        const int nst = 6;
        // prologue: first 3 W stages
        #pragma unroll
        for (int s = 0; s < 3; s++) {
            conv_issueW(s, sb + W_OFF + s*WSZ, tid);
            CPA_COMMIT();
        }
        CPA_WAIT(2);              // A + W stage0 complete
        __syncthreads();
        for (int s = 0; s < nst; s++) {
            int k = s;
            uint32_t abase = sb + A_OFF + (wm*32 + k + lr)*PITCH + lh*16;
            uint32_t bbase = sb + W_OFF + (s % 3)*WSZ + (wn*64 + lr)*PITCH + lh*16;
            #pragma unroll
            for (int kc = 0; kc < 8; kc++) {
                uint32_t a[2][4];
                ldsm_x4(a[0], abase + kc*32);
                ldsm_x4(a[1], abase + kc*32 + 16*PITCH);
                #pragma unroll
                for (int ntp = 0; ntp < 4; ntp++) {
                    uint32_t bf[4];
                    ldsm_x4(bf, bbase + ntp*16*PITCH + kc*32);
                    #pragma unroll
                    for (int mt = 0; mt < 2; mt++) {
                        mma16816(c[mt][2*ntp],     a[mt], bf[0], bf[2]);
                        mma16816(c[mt][2*ntp + 1], a[mt], bf[1], bf[3]);
                    }
                }
            }
            __syncthreads();       // everyone done with buffer s%3
            if (s + 3 < nst) {
                conv_issueW(s + 3, sb + W_OFF + ((s+3) % 3)*WSZ, tid);
                CPA_COMMIT();
            }
            if (s + 1 < nst) {
                CPA_WAIT(2);       // stage s+1 complete
                __syncthreads();
            }
        }
        CPA_WAIT(0);
        __syncthreads();
    }

    // epilogue: bias, store, fused per-block channel max
    int pbase = nb*512 + p0loc + wm*32 + (lane >> 2);
    #pragma unroll
    for (int nt = 0; nt < 8; nt++) {
        int col = wn*64 + nt*8 + (lane & 3)*2;
        float2 b2 = *(const float2*)(cb + col);
        float mx = -INFINITY, my = -INFINITY;
        #pragma unroll
        for (int mt = 0; mt < 2; mt++) {
            float x0 = c[mt][nt][0] + b2.x, y0 = c[mt][nt][1] + b2.y;
            float x1 = c[mt][nt][2] + b2.x, y1 = c[mt][nt][3] + b2.y;
            int row = pbase + mt*16;
            *(float2*)(g_conv + ((size_t)row << 7) + col)       = make_float2(x0, y0);
            *(float2*)(g_conv + ((size_t)(row + 8) << 7) + col) = make_float2(x1, y1);
            mx = fmaxf(mx, fmaxf(x0, x1));
            my = fmaxf(my, fmaxf(y0, y1));
        }
        #pragma unroll
        for (int o = 4; o < 32; o <<= 1) {
            mx = fmaxf(mx, __shfl_xor_sync(~0u, mx, o));
            my = fmaxf(my, __shfl_xor_sync(~0u, my, o));
        }
        if (lane < 4) {
            int cg = wn*64 + nt*8 + lane*2;
            atomicMax(&g_repr[nb*DD + cg],     enc_f(mx));
            atomicMax(&g_repr[nb*DD + cg + 1], enc_f(my));
        }
    }
}

// ---------------- K6: a_s = attn(block_repr, blocks_c, blocks_c) ----------------
__global__ void k_attn_s() {
    int n = blockIdx.x, tid = threadIdx.x;
    int lane = tid & 31, w = tid >> 5;
    __shared__ float s[BSB];
    __shared__ float red[128];
    float4 q4;
    q4.x = dec_f(g_repr[n*DD + lane*4 + 0]);
    q4.y = dec_f(g_repr[n*DD + lane*4 + 1]);
    q4.z = dec_f(g_repr[n*DD + lane*4 + 2]);
    q4.w = dec_f(g_repr[n*DD + lane*4 + 3]);
    const float* kv = g_conv + (size_t)n * BSB * DD;
    for (int j = w; j < BSB; j += 4) {
        float4 k4 = *(const float4*)&kv[(size_t)j*DD + lane*4];
        float p = q4.x*k4.x + q4.y*k4.y + q4.z*k4.z + q4.w*k4.w;
        #pragma unroll
        for (int o = 16; o; o >>= 1) p += __shfl_xor_sync(~0u, p, o);
        if (lane == 0) s[j] = p * SCALEF;
    }
    __syncthreads();
    float mx = -INFINITY;
    for (int j = tid; j < BSB; j += 128) mx = fmaxf(mx, s[j]);
    red[tid] = mx; __syncthreads();
    for (int st = 64; st; st >>= 1) { if (tid < st) red[tid] = fmaxf(red[tid], red[tid+st]); __syncthreads(); }
    float M = red[0]; __syncthreads();
    float sm = 0.f;
    for (int j = tid; j < BSB; j += 128) { float e = expf(s[j] - M); s[j] = e; sm += e; }
    red[tid] = sm; __syncthreads();
    for (int st = 64; st; st >>= 1) { if (tid < st) red[tid] += red[tid+st]; __syncthreads(); }
    float SUM = red[0]; __syncthreads();
    float acc = 0.f;
    #pragma unroll 4
    for (int j = 0; j < BSB; j++) acc += s[j] * kv[(size_t)j*DD + tid];
    g_as[n*DD + tid] = acc / SUM;
}

// ---------------- K7: a_o = attn(block_repr, xbo, xbo) ----------------
__global__ void k_attn_o() {
    int n = blockIdx.x, tid = threadIdx.x;
    int lane = tid & 31, w = tid >> 5;
    int bq = n >> 6, c = n & 63;
    __shared__ float s[128];
    __shared__ float red[128];
    float qa[4];
    #pragma unroll
    for (int q = 0; q < 4; q++) qa[q] = dec_f(g_repr[n*DD + lane*4 + q]);
    for (int j = w; j < 128; j += 4) {
        int tt = 448 + c*BSB + j; if (tt > LTOK-1) tt = LTOK-1;
        size_t ro = ((size_t)bq*LTOK + tt) << 7;
        float p = 0.f;
        #pragma unroll
        for (int q = 0; q < 4; q++) {
            int chn = lane*4 + q;
            float kvv = __half2float(g_ph[ro + chn]) + __half2float(g_pl[ro + chn]);
            p += qa[q] * kvv;
        }
        #pragma unroll
        for (int o = 16; o; o >>= 1) p += __shfl_xor_sync(~0u, p, o);
        if (lane == 0) s[j] = p * SCALEF;
    }
    __syncthreads();
    red[tid] = s[tid]; __syncthreads();
    for (int st = 64; st; st >>= 1) { if (tid < st) red[tid] = fmaxf(red[tid], red[tid+st]); __syncthreads(); }
    float M = red[0]; __syncthreads();
    float e = expf(s[tid] - M); s[tid] = e;
    red[tid] = e; __syncthreads();
    for (int st = 64; st; st >>= 1) { if (tid < st) red[tid] += red[tid+st]; __syncthreads(); }
    float SUM = red[0]; __syncthreads();
    float acc = 0.f;
    for (int j = 0; j < 128; j++) {
        int tt = 448 + c*BSB + j; if (tt > LTOK-1) tt = LTOK-1;
        size_t ro = ((size_t)bq*LTOK + tt) << 7;
        acc += s[j] * (__half2float(g_ph[ro + tid]) + __half2float(g_pl[ro + tid]));
    }
    g_ao[n*DD + tid] = acc / SUM;
}

// ---------------- K8: fusion GEMV ----------------
__global__ void k_fuse(const float* __restrict__ fw, const float* __restrict__ fb,
                       float* __restrict__ out, int out_size) {
    int n = blockIdx.x, o = threadIdx.x;
    __shared__ float f[384];
    f[o]       = g_as[n*DD + o];
    f[128 + o] = g_ao[n*DD + o];
    f[256 + o] = dec_f(g_repr[n*DD + o]);
    __syncthreads();
    float acc = fb[o];
    #pragma unroll 4
    for (int i = 0; i < 384; i++) acc += f[i] * fw[i*DD + o];
    for (int off = 0; off + NBL*DD <= out_size; off += NBL*DD)
        out[off + n*DD + o] = acc;
}

// ---------------- launch ----------------
extern "C" void kernel_launch(void* const* d_in, const int* in_sizes, int n_in,
                              void* d_out, int out_size) {
    const float* x        = (const float*)d_in[0];
    const float* w_lw     = (const float*)d_in[1];
    const float* b_lw     = (const float*)d_in[2];
    const float* conv_w   = (const float*)d_in[3];
    const float* conv_b   = (const float*)d_in[4];
    const float* fusion_w = (const float*)d_in[5];
    const float* fusion_b = (const float*)d_in[6];
    float* out = (float*)d_out;

    cudaFuncSetAttribute(k_conv, cudaFuncAttributeMaxDynamicSharedMemorySize, CONV_SMEM);

    k_wt<<<96, 1024>>>(conv_w);
    k_init_repr<<<64, 1024>>>();
    k_logits<<<BB*LTOK/8, 256>>>(x, w_lw, b_lw);
    k_cmax<<<dim3(NCH, BB), 256>>>();
    k_cmaxscan<<<1, 8>>>();
    k_escan<<<dim3(NCH, BB), 512>>>();
    k_csscan<<<1, 8>>>();
    k_rfin<<<dim3(NCH, BB), 512>>>();
    k_chunksum<<<dim3(NCH, BB), 128>>>(x);
    k_chscan<<<1, 1024>>>();
    k_prefix<<<dim3(NCH, BB), 128>>>(x);
    k_conv<<<1024, 512, CONV_SMEM>>>(conv_b);
    k_attn_s<<<NBL, 128>>>();
    k_attn_o<<<NBL, 128>>>();
    k_fuse<<<NBL, 128>>>(fusion_w, fusion_b, out, out_size);
}

// round 8
// speedup vs baseline: 3.0165x; 1.2609x over previous
#include <cuda_runtime.h>
#include <cuda_fp16.h>
#include <math.h>
#include <stdint.h>

#define BB   8
#define LTOK 32768
#define DD   128
#define BSB  512
#define NBL  512
#define KW   6
#define NCH  64
#define SCALEF 0.08838834764831845f

// ---------------- device scratch ----------------
__device__ float    g_logits[BB*LTOK];
__device__ float    g_e[BB*LTOK];
__device__ float    g_r[BB*LTOK];
__device__ float    g_cm[BB*NCH];
__device__ float    g_cm0[BB*NCH];
__device__ float    g_cs[BB*NCH];
__device__ float    g_cp0[BB*NCH];
__device__ float    g_csum[BB*NCH*DD];
__device__ __align__(16) __half g_ph[(size_t)BB*LTOK*DD];   // prefix hi (fp16)
__device__ __align__(16) __half g_pl[(size_t)BB*LTOK*DD];   // prefix lo (fp16)
__device__ float    g_conv[(size_t)NBL*BSB*DD];
__device__ unsigned g_repr[NBL*DD];
__device__ float    g_as[NBL*DD];
__device__ float    g_ao[NBL*DD];
__device__ __align__(16) __half g_wh[KW*DD*DD];  // [k][o][i], fp16

// ---------------- helpers ----------------
__device__ __forceinline__ unsigned enc_f(float f) {
    unsigned u = __float_as_uint(f);
    return (u & 0x80000000u) ? ~u : (u | 0x80000000u);
}
__device__ __forceinline__ float dec_f(unsigned u) {
    u = (u & 0x80000000u) ? (u & 0x7fffffffu) : ~u;
    return __uint_as_float(u);
}
__device__ __forceinline__ uint32_t smem_u32(const void* p) {
    uint32_t a;
    asm("{ .reg .u64 t; cvta.to.shared.u64 t, %1; cvt.u32.u64 %0, t; }" : "=r"(a) : "l"(p));
    return a;
}
__device__ __forceinline__ void ldsm_x4(uint32_t* r, uint32_t addr) {
    asm volatile("ldmatrix.sync.aligned.m8n8.x4.shared.b16 {%0,%1,%2,%3}, [%4];"
        : "=r"(r[0]), "=r"(r[1]), "=r"(r[2]), "=r"(r[3]) : "r"(addr));
}
__device__ __forceinline__ void mma16816(float* c, const uint32_t* a, uint32_t b0, uint32_t b1) {
    asm volatile(
        "mma.sync.aligned.m16n8k16.row.col.f32.f16.f16.f32 "
        "{%0,%1,%2,%3}, {%4,%5,%6,%7}, {%8,%9}, {%0,%1,%2,%3};"
        : "+f"(c[0]), "+f"(c[1]), "+f"(c[2]), "+f"(c[3])
        : "r"(a[0]), "r"(a[1]), "r"(a[2]), "r"(a[3]), "r"(b0), "r"(b1));
}
__device__ __forceinline__ void cpa16(uint32_t dst, const void* src) {
    asm volatile("cp.async.cg.shared.global [%0], [%1], 16;" :: "r"(dst), "l"(src) : "memory");
}
__device__ __forceinline__ void cpa16z(uint32_t dst, const void* src, int srcsize) {
    asm volatile("cp.async.cg.shared.global [%0], [%1], 16, %2;" :: "r"(dst), "l"(src), "r"(srcsize) : "memory");
}
#define CPA_COMMIT() asm volatile("cp.async.commit_group;" ::: "memory")
#define CPA_WAIT(n)  asm volatile("cp.async.wait_group %0;" :: "n"(n) : "memory")

// ---------------- K0: conv weights -> fp16 [k][o][i] ----------------
__global__ void k_wt(const float* __restrict__ cw) {
    int idx = blockIdx.x * blockDim.x + threadIdx.x;
    if (idx < KW*DD*DD) {
        int i = idx & 127;
        int r = idx >> 7;
        int o = r & 127;
        int kk = r >> 7;
        g_wh[idx] = __float2half(cw[o*768 + i*6 + kk]);
    }
}

__global__ void k_init_repr() {
    int i = blockIdx.x * blockDim.x + threadIdx.x;
    if (i < NBL*DD) g_repr[i] = 0u;
}

// ---------------- K1: logits = silu(x @ w + b) ----------------
__global__ void k_logits(const float* __restrict__ x, const float* __restrict__ w,
                         const float* __restrict__ bl) {
    int gw = blockIdx.x * (blockDim.x >> 5) + (threadIdx.x >> 5);
    int lane = threadIdx.x & 31;
    if (gw >= BB*LTOK) return;
    float4 xv = *(const float4*)&x[(size_t)gw*DD + lane*4];
    float4 wv = *(const float4*)&w[lane*4];
    float s = xv.x*wv.x + xv.y*wv.y + xv.z*wv.z + xv.w*wv.w;
    #pragma unroll
    for (int o = 16; o; o >>= 1) s += __shfl_xor_sync(~0u, s, o);
    if (lane == 0) {
        float z = s + bl[0];
        g_logits[gw] = z / (1.f + expf(-z));
    }
}

// ---------------- parallel scan (chunked) ----------------
template<bool MX>
__device__ __forceinline__ float iscan512(float v, float* ws) {
    int lane = threadIdx.x & 31, w = threadIdx.x >> 5;
    float x = v;
    #pragma unroll
    for (int o = 1; o < 32; o <<= 1) {
        float y = __shfl_up_sync(~0u, x, o);
        if (lane >= o) x = MX ? fmaxf(x, y) : (x + y);
    }
    if (lane == 31) ws[w] = x;
    __syncthreads();
    if (w == 0 && lane < 16) {
        float t = ws[lane];
        #pragma unroll
        for (int o = 1; o < 16; o <<= 1) {
            float y = __shfl_up_sync(0xFFFFu, t, o);
            if (lane >= o) t = MX ? fmaxf(t, y) : (t + y);
        }
        ws[lane] = t;
    }
    __syncthreads();
    if (w > 0) {
        float pre = ws[w-1];
        x = MX ? fmaxf(x, pre) : (x + pre);
    }
    return x;
}

__global__ void k_cmax() {
    __shared__ float red[256];
    int c = blockIdx.x, b = blockIdx.y, t = threadIdx.x;
    int base = b*LTOK + c*BSB;
    float v = fmaxf(g_logits[base + t], g_logits[base + t + 256]);
    red[t] = v; __syncthreads();
    for (int st = 128; st; st >>= 1) { if (t < st) red[t] = fmaxf(red[t], red[t+st]); __syncthreads(); }
    if (t == 0) g_cm[b*NCH + c] = red[0];
}
__global__ void k_cmaxscan() {
    int b = threadIdx.x; if (b >= BB) return;
    float run = -INFINITY;
    for (int c = 0; c < NCH; c++) {
        g_cm0[b*NCH + c] = run;
        run = fmaxf(run, g_cm[b*NCH + c]);
    }
}
__global__ __launch_bounds__(512) void k_escan() {
    __shared__ float ws[16];
    int c = blockIdx.x, b = blockIdx.y, t = threadIdx.x;
    int base = b*LTOK + c*BSB;
    float l = g_logits[base + t];
    float lm = iscan512<true>(l, ws);
    float M = fmaxf(lm, g_cm0[b*NCH + c]);
    float e = expf(l - M);
    g_e[base + t] = e;
    __syncthreads();
    float S = iscan512<false>(e, ws);
    if (t == 511) g_cs[b*NCH + c] = S;
}
__global__ void k_csscan() {
    int b = threadIdx.x; if (b >= BB) return;
    float run = 0.f;
    for (int c = 0; c < NCH; c++) {
        g_cp0[b*NCH + c] = run;
        run += g_cs[b*NCH + c];
    }
}
__global__ __launch_bounds__(512) void k_rfin() {
    __shared__ float ws[16];
    int c = blockIdx.x, b = blockIdx.y, t = threadIdx.x;
    int base = b*LTOK + c*BSB;
    float e = g_e[base + t];
    float P = iscan512<false>(e, ws) + g_cp0[b*NCH + c];
    g_r[base + t] = 1.f / P;
}

// ---------------- K3a: chunk partial sums of e*x ----------------
__global__ void k_chunksum(const float* __restrict__ x) {
    int ch = blockIdx.x, b = blockIdx.y, d = threadIdx.x;
    __shared__ float es[BSB];
    size_t base = (size_t)b * LTOK + (size_t)ch * BSB;
    for (int t = d; t < BSB; t += DD) es[t] = g_e[base + t];
    __syncthreads();
    const float* xp = x + base * DD + d;
    float a0 = 0, a1 = 0, a2 = 0, a3 = 0;
    for (int t = 0; t < BSB; t += 4) {
        a0 += es[t+0] * xp[(size_t)(t+0)*DD];
        a1 += es[t+1] * xp[(size_t)(t+1)*DD];
        a2 += es[t+2] * xp[(size_t)(t+2)*DD];
        a3 += es[t+3] * xp[(size_t)(t+3)*DD];
    }
    g_csum[(b*NCH + ch)*DD + d] = (a0 + a1) + (a2 + a3);
}

__global__ void k_chscan() {
    int id = threadIdx.x;            // 1024 = 8*128
    int b = id >> 7, d = id & 127;
    float run = 0.f;
    for (int ch = 0; ch < NCH; ch++) {
        int idx = (b*NCH + ch)*DD + d;
        float v = g_csum[idx];
        g_csum[idx] = run;
        run += v;
    }
}

// ---------------- K3c: finalize prefix -> fp16 hi/lo ----------------
__global__ void k_prefix(const float* __restrict__ x) {
    int ch = blockIdx.x, b = blockIdx.y, d = threadIdx.x;
    __shared__ float es[BSB], rs[BSB];
    size_t base = (size_t)b * LTOK + (size_t)ch * BSB;
    for (int t = d; t < BSB; t += DD) { es[t] = g_e[base + t]; rs[t] = g_r[base + t]; }
    __syncthreads();
    float run = g_csum[(b*NCH + ch)*DD + d];
    const float* xp = x + base * DD + d;
    __half* ph = g_ph + base * DD + d;
    __half* pl = g_pl + base * DD + d;
    #pragma unroll 4
    for (int t = 0; t < BSB; t++) {
        float xv = xp[(size_t)t*DD];
        run += es[t] * xv;
        float pv = run * rs[t] + xv;
        __half h = __float2half(pv);
        ph[(size_t)t*DD] = h;
        pl[(size_t)t*DD] = __float2half(pv - __half2float(h));
    }
}

// ---------------- K4: conv1d via mma.sync fp16 single-pass (xh*wh) ----------
// Single phase: A = hi plane, 6 W stages (k=0..5), W triple-buffered cp.async.
#define PITCH 272
#define A_OFF 0                 // 261*272 = 70992
#define W_OFF 71040
#define WSZ   34816             // 128*272
#define CONV_SMEM (W_OFF + 3*WSZ)   // 175488
__device__ __forceinline__ void conv_issueW(int k, uint32_t dstbase, int tid) {
    #pragma unroll
    for (int u = 0; u < 4; u++) {
        int t = tid + u*512;
        int o = t >> 4, cc = (t & 15) << 3;
        cpa16(dstbase + o*PITCH + cc*2, g_wh + (((size_t)(k*128 + o)) << 7) + cc);
    }
}
__global__ __launch_bounds__(512, 1) void k_conv(const float* __restrict__ cb) {
    extern __shared__ char sm[];
    uint32_t sb = smem_u32(sm);
    int tid = threadIdx.x, lane = tid & 31, wid = tid >> 5;
    int wm = wid >> 1, wn = wid & 1;
    int nb = blockIdx.x >> 1;
    int p0loc = (blockIdx.x & 1) << 8;
    int lr = lane & 15, lh = lane >> 4;

    float c[2][8][4];
    #pragma unroll
    for (int mt = 0; mt < 2; mt++)
        #pragma unroll
        for (int nt = 0; nt < 8; nt++)
            #pragma unroll
            for (int v = 0; v < 4; v++) c[mt][nt][v] = 0.f;

    // stage A (hi plane only)
    for (int t = tid; t < 261*16; t += 512) {
        int r = t >> 4, cc = (t & 15) << 3;
        int q = p0loc + r - 2;
        const void* src = g_ph;
        int sz = 0;
        if (q >= 0 && q < 512) {
            src = g_ph + ((((size_t)nb << 9) + q) << 7) + cc;
            sz = 16;
        }
        cpa16z(sb + A_OFF + r*PITCH + cc*2, src, sz);
    }
    CPA_COMMIT();
    const int nst = 6;
    // prologue: first 3 W stages
    #pragma unroll
    for (int s = 0; s < 3; s++) {
        conv_issueW(s, sb + W_OFF + s*WSZ, tid);
        CPA_COMMIT();
    }
    CPA_WAIT(2);              // A + W stage0 complete
    __syncthreads();
    for (int s = 0; s < nst; s++) {
        int k = s;
        uint32_t abase = sb + A_OFF + (wm*32 + k + lr)*PITCH + lh*16;
        uint32_t bbase = sb + W_OFF + (s % 3)*WSZ + (wn*64 + lr)*PITCH + lh*16;
        #pragma unroll
        for (int kc = 0; kc < 8; kc++) {
            uint32_t a[2][4];
            ldsm_x4(a[0], abase + kc*32);
            ldsm_x4(a[1], abase + kc*32 + 16*PITCH);
            #pragma unroll
            for (int ntp = 0; ntp < 4; ntp++) {
                uint32_t bf[4];
                ldsm_x4(bf, bbase + ntp*16*PITCH + kc*32);
                #pragma unroll
                for (int mt = 0; mt < 2; mt++) {
                    mma16816(c[mt][2*ntp],     a[mt], bf[0], bf[2]);
                    mma16816(c[mt][2*ntp + 1], a[mt], bf[1], bf[3]);
                }
            }
        }
        __syncthreads();       // everyone done with buffer s%3
        if (s + 3 < nst) {
            conv_issueW(s + 3, sb + W_OFF + ((s+3) % 3)*WSZ, tid);
            CPA_COMMIT();
        }
        if (s + 1 < nst) {
            CPA_WAIT(2);       // stage s+1 complete
            __syncthreads();
        }
    }
    CPA_WAIT(0);
    __syncthreads();

    // epilogue: bias, store, fused per-block channel max
    int pbase = nb*512 + p0loc + wm*32 + (lane >> 2);
    #pragma unroll
    for (int nt = 0; nt < 8; nt++) {
        int col = wn*64 + nt*8 + (lane & 3)*2;
        float2 b2 = *(const float2*)(cb + col);
        float mx = -INFINITY, my = -INFINITY;
        #pragma unroll
        for (int mt = 0; mt < 2; mt++) {
            float x0 = c[mt][nt][0] + b2.x, y0 = c[mt][nt][1] + b2.y;
            float x1 = c[mt][nt][2] + b2.x, y1 = c[mt][nt][3] + b2.y;
            int row = pbase + mt*16;
            *(float2*)(g_conv + ((size_t)row << 7) + col)       = make_float2(x0, y0);
            *(float2*)(g_conv + ((size_t)(row + 8) << 7) + col) = make_float2(x1, y1);
            mx = fmaxf(mx, fmaxf(x0, x1));
            my = fmaxf(my, fmaxf(y0, y1));
        }
        #pragma unroll
        for (int o = 4; o < 32; o <<= 1) {
            mx = fmaxf(mx, __shfl_xor_sync(~0u, mx, o));
            my = fmaxf(my, __shfl_xor_sync(~0u, my, o));
        }
        if (lane < 4) {
            int cg = wn*64 + nt*8 + lane*2;
            atomicMax(&g_repr[nb*DD + cg],     enc_f(mx));
            atomicMax(&g_repr[nb*DD + cg + 1], enc_f(my));
        }
    }
}

// ---------------- K6: a_s = attn(block_repr, blocks_c, blocks_c) ----------------
__global__ void k_attn_s() {
    int n = blockIdx.x, tid = threadIdx.x;
    int lane = tid & 31, w = tid >> 5;
    __shared__ float s[BSB];
    __shared__ float red[128];
    float4 q4;
    q4.x = dec_f(g_repr[n*DD + lane*4 + 0]);
    q4.y = dec_f(g_repr[n*DD + lane*4 + 1]);
    q4.z = dec_f(g_repr[n*DD + lane*4 + 2]);
    q4.w = dec_f(g_repr[n*DD + lane*4 + 3]);
    const float* kv = g_conv + (size_t)n * BSB * DD;
    for (int j = w; j < BSB; j += 4) {
        float4 k4 = *(const float4*)&kv[(size_t)j*DD + lane*4];
        float p = q4.x*k4.x + q4.y*k4.y + q4.z*k4.z + q4.w*k4.w;
        #pragma unroll
        for (int o = 16; o; o >>= 1) p += __shfl_xor_sync(~0u, p, o);
        if (lane == 0) s[j] = p * SCALEF;
    }
    __syncthreads();
    float mx = -INFINITY;
    for (int j = tid; j < BSB; j += 128) mx = fmaxf(mx, s[j]);
    red[tid] = mx; __syncthreads();
    for (int st = 64; st; st >>= 1) { if (tid < st) red[tid] = fmaxf(red[tid], red[tid+st]); __syncthreads(); }
    float M = red[0]; __syncthreads();
    float sm = 0.f;
    for (int j = tid; j < BSB; j += 128) { float e = expf(s[j] - M); s[j] = e; sm += e; }
    red[tid] = sm; __syncthreads();
    for (int st = 64; st; st >>= 1) { if (tid < st) red[tid] += red[tid+st]; __syncthreads(); }
    float SUM = red[0]; __syncthreads();
    float acc = 0.f;
    #pragma unroll 4
    for (int j = 0; j < BSB; j++) acc += s[j] * kv[(size_t)j*DD + tid];
    g_as[n*DD + tid] = acc / SUM;
}

// ---------------- K7: a_o = attn(block_repr, xbo, xbo) ----------------
__global__ void k_attn_o() {
    int n = blockIdx.x, tid = threadIdx.x;
    int lane = tid & 31, w = tid >> 5;
    int bq = n >> 6, c = n & 63;
    __shared__ float s[128];
    __shared__ float red[128];
    float qa[4];
    #pragma unroll
    for (int q = 0; q < 4; q++) qa[q] = dec_f(g_repr[n*DD + lane*4 + q]);
    for (int j = w; j < 128; j += 4) {
        int tt = 448 + c*BSB + j; if (tt > LTOK-1) tt = LTOK-1;
        size_t ro = ((size_t)bq*LTOK + tt) << 7;
        float p = 0.f;
        #pragma unroll
        for (int q = 0; q < 4; q++) {
            int chn = lane*4 + q;
            float kvv = __half2float(g_ph[ro + chn]) + __half2float(g_pl[ro + chn]);
            p += qa[q] * kvv;
        }
        #pragma unroll
        for (int o = 16; o; o >>= 1) p += __shfl_xor_sync(~0u, p, o);
        if (lane == 0) s[j] = p * SCALEF;
    }
    __syncthreads();
    red[tid] = s[tid]; __syncthreads();
    for (int st = 64; st; st >>= 1) { if (tid < st) red[tid] = fmaxf(red[tid], red[tid+st]); __syncthreads(); }
    float M = red[0]; __syncthreads();
    float e = expf(s[tid] - M); s[tid] = e;
    red[tid] = e; __syncthreads();
    for (int st = 64; st; st >>= 1) { if (tid < st) red[tid] += red[tid+st]; __syncthreads(); }
    float SUM = red[0]; __syncthreads();
    float acc = 0.f;
    for (int j = 0; j < 128; j++) {
        int tt = 448 + c*BSB + j; if (tt > LTOK-1) tt = LTOK-1;
        size_t ro = ((size_t)bq*LTOK + tt) << 7;
        acc += s[j] * (__half2float(g_ph[ro + tid]) + __half2float(g_pl[ro + tid]));
    }
    g_ao[n*DD + tid] = acc / SUM;
}

// ---------------- K8: fusion GEMV ----------------
__global__ void k_fuse(const float* __restrict__ fw, const float* __restrict__ fb,
                       float* __restrict__ out, int out_size) {
    int n = blockIdx.x, o = threadIdx.x;
    __shared__ float f[384];
    f[o]       = g_as[n*DD + o];
    f[128 + o] = g_ao[n*DD + o];
    f[256 + o] = dec_f(g_repr[n*DD + o]);
    __syncthreads();
    float acc = fb[o];
    #pragma unroll 4
    for (int i = 0; i < 384; i++) acc += f[i] * fw[i*DD + o];
    for (int off = 0; off + NBL*DD <= out_size; off += NBL*DD)
        out[off + n*DD + o] = acc;
}

// ---------------- launch ----------------
extern "C" void kernel_launch(void* const* d_in, const int* in_sizes, int n_in,
                              void* d_out, int out_size) {
    const float* x        = (const float*)d_in[0];
    const float* w_lw     = (const float*)d_in[1];
    const float* b_lw     = (const float*)d_in[2];
    const float* conv_w   = (const float*)d_in[3];
    const float* conv_b   = (const float*)d_in[4];
    const float* fusion_w = (const float*)d_in[5];
    const float* fusion_b = (const float*)d_in[6];
    float* out = (float*)d_out;

    cudaFuncSetAttribute(k_conv, cudaFuncAttributeMaxDynamicSharedMemorySize, CONV_SMEM);

    k_wt<<<96, 1024>>>(conv_w);
    k_init_repr<<<64, 1024>>>();
    k_logits<<<BB*LTOK/8, 256>>>(x, w_lw, b_lw);
    k_cmax<<<dim3(NCH, BB), 256>>>();
    k_cmaxscan<<<1, 8>>>();
    k_escan<<<dim3(NCH, BB), 512>>>();
    k_csscan<<<1, 8>>>();
    k_rfin<<<dim3(NCH, BB), 512>>>();
    k_chunksum<<<dim3(NCH, BB), 128>>>(x);
    k_chscan<<<1, 1024>>>();
    k_prefix<<<dim3(NCH, BB), 128>>>(x);
    k_conv<<<1024, 512, CONV_SMEM>>>(conv_b);
    k_attn_s<<<NBL, 128>>>();
    k_attn_o<<<NBL, 128>>>();
    k_fuse<<<NBL, 128>>>(fusion_w, fusion_b, out, out_size);
}

// round 9
// speedup vs baseline: 3.3965x; 1.1260x over previous
#include <cuda_runtime.h>
#include <cuda_fp16.h>
#include <math.h>
#include <stdint.h>

#define BB   8
#define LTOK 32768
#define DD   128
#define BSB  512
#define NBL  512
#define KW   6
#define NCH  64
#define SCALEF 0.08838834764831845f

// ---------------- device scratch ----------------
__device__ __align__(16) __half g_ph[(size_t)BB*LTOK*DD];   // prefix hi (fp16)
__device__ __align__(16) __half g_pl[(size_t)BB*LTOK*DD];   // prefix lo (fp16)
__device__ float    g_conv[(size_t)NBL*BSB*DD];
__device__ unsigned g_repr[NBL*DD];
__device__ float    g_as[NBL*DD];
__device__ float    g_ao[NBL*DD];
__device__ __align__(16) __half g_wh[KW*DD*DD];  // [k][o][i], fp16
// decoupled-lookback state
__device__ float    g_aggmax[BB*NCH], g_incmax[BB*NCH];
__device__ float    g_aggsum[BB*NCH], g_incsum[BB*NCH];
__device__ float    g_aggch[BB*NCH*DD], g_incch[BB*NCH*DD];
__device__ unsigned g_f1[BB*NCH], g_f2[BB*NCH], g_f3[BB*NCH];

// ---------------- helpers ----------------
__device__ __forceinline__ unsigned enc_f(float f) {
    unsigned u = __float_as_uint(f);
    return (u & 0x80000000u) ? ~u : (u | 0x80000000u);
}
__device__ __forceinline__ float dec_f(unsigned u) {
    u = (u & 0x80000000u) ? (u & 0x7fffffffu) : ~u;
    return __uint_as_float(u);
}
__device__ __forceinline__ uint32_t smem_u32(const void* p) {
    uint32_t a;
    asm("{ .reg .u64 t; cvta.to.shared.u64 t, %1; cvt.u32.u64 %0, t; }" : "=r"(a) : "l"(p));
    return a;
}
__device__ __forceinline__ void st_release(unsigned* p, unsigned v) {
    asm volatile("st.release.gpu.u32 [%0], %1;" :: "l"(p), "r"(v) : "memory");
}
__device__ __forceinline__ unsigned ld_acquire(unsigned* p) {
    unsigned v;
    asm volatile("ld.acquire.gpu.u32 %0, [%1];" : "=r"(v) : "l"(p) : "memory");
    return v;
}
__device__ __forceinline__ void ldsm_x4(uint32_t* r, uint32_t addr) {
    asm volatile("ldmatrix.sync.aligned.m8n8.x4.shared.b16 {%0,%1,%2,%3}, [%4];"
        : "=r"(r[0]), "=r"(r[1]), "=r"(r[2]), "=r"(r[3]) : "r"(addr));
}
__device__ __forceinline__ void mma16816(float* c, const uint32_t* a, uint32_t b0, uint32_t b1) {
    asm volatile(
        "mma.sync.aligned.m16n8k16.row.col.f32.f16.f16.f32 "
        "{%0,%1,%2,%3}, {%4,%5,%6,%7}, {%8,%9}, {%0,%1,%2,%3};"
        : "+f"(c[0]), "+f"(c[1]), "+f"(c[2]), "+f"(c[3])
        : "r"(a[0]), "r"(a[1]), "r"(a[2]), "r"(a[3]), "r"(b0), "r"(b1));
}
__device__ __forceinline__ void cpa16(uint32_t dst, const void* src) {
    asm volatile("cp.async.cg.shared.global [%0], [%1], 16;" :: "r"(dst), "l"(src) : "memory");
}
__device__ __forceinline__ void cpa16z(uint32_t dst, const void* src, int srcsize) {
    asm volatile("cp.async.cg.shared.global [%0], [%1], 16, %2;" :: "r"(dst), "l"(src), "r"(srcsize) : "memory");
}
#define CPA_COMMIT() asm volatile("cp.async.commit_group;" ::: "memory")
#define CPA_WAIT(n)  asm volatile("cp.async.wait_group %0;" :: "n"(n) : "memory")

// ---------------- K0: conv weights -> fp16 [k][o][i] ----------------
__global__ void k_wt(const float* __restrict__ cw) {
    int idx = blockIdx.x * blockDim.x + threadIdx.x;
    if (idx < KW*DD*DD) {
        int i = idx & 127;
        int r = idx >> 7;
        int o = r & 127;
        int kk = r >> 7;
        g_wh[idx] = __float2half(cw[o*768 + i*6 + kk]);
    }
}

// ---------------- K0b: init repr + lookback flags ----------------
__global__ void k_init() {
    int i = blockIdx.x * blockDim.x + threadIdx.x;
    if (i < NBL*DD) g_repr[i] = 0u;
    if (i < BB*NCH) { g_f1[i] = 0u; g_f2[i] = 0u; g_f3[i] = 0u; }
}

// ---------------- 512-thread inclusive scan ----------------
template<bool MX>
__device__ __forceinline__ float iscan512(float v, float* ws) {
    int lane = threadIdx.x & 31, w = threadIdx.x >> 5;
    float x = v;
    #pragma unroll
    for (int o = 1; o < 32; o <<= 1) {
        float y = __shfl_up_sync(~0u, x, o);
        if (lane >= o) x = MX ? fmaxf(x, y) : (x + y);
    }
    if (lane == 31) ws[w] = x;
    __syncthreads();
    if (w == 0 && lane < 16) {
        float t = ws[lane];
        #pragma unroll
        for (int o = 1; o < 16; o <<= 1) {
            float y = __shfl_up_sync(0xFFFFu, t, o);
            if (lane >= o) t = MX ? fmaxf(t, y) : (t + y);
        }
        ws[lane] = t;
    }
    __syncthreads();
    if (w > 0) {
        float pre = ws[w-1];
        x = MX ? fmaxf(x, pre) : (x + pre);
    }
    return x;
}

// ---------------- K1: fused prefix pipeline (logits -> scans -> prefix) ----------
// grid (NCH, BB), 512 threads. Decoupled lookback across chunks.
__global__ __launch_bounds__(512) void k_pre(const float* __restrict__ x,
                                             const float* __restrict__ w,
                                             const float* __restrict__ bl) {
    __shared__ float sl[512];
    __shared__ float se[512];
    __shared__ float sr[512];
    __shared__ float sP[512];    // [q][d] quarter channel partials
    __shared__ float sPre[128];
    __shared__ float sAgg[128];
    __shared__ float ws[16];
    __shared__ float sbc[2];
    int c = blockIdx.x, b = blockIdx.y;
    int bc = b*NCH + c;
    int tid = threadIdx.x, lane = tid & 31, wid = tid >> 5;
    size_t base = (size_t)b*LTOK + (size_t)c*BSB;

    // --- logits: 16 warps x 32 rows ---
    float4 wv = *(const float4*)&w[lane*4];
    float bb = bl[0];
    for (int r0 = wid; r0 < 512; r0 += 16) {
        float4 xv = *(const float4*)&x[(base + r0)*DD + lane*4];
        float s = xv.x*wv.x + xv.y*wv.y + xv.z*wv.z + xv.w*wv.w;
        #pragma unroll
        for (int o = 16; o; o >>= 1) s += __shfl_xor_sync(~0u, s, o);
        if (lane == 0) {
            float z = s + bb;
            sl[r0] = z / (1.f + expf(-z));
        }
    }
    __syncthreads();

    // --- inclusive cummax + max lookback ---
    float l = sl[tid];
    float lm = iscan512<true>(l, ws);
    if (tid == 511) sbc[0] = lm;
    __syncthreads();
    if (tid == 0) {
        float own = sbc[0];
        g_aggmax[bc] = own;
        __threadfence();
        st_release(&g_f1[bc], 1);
        float pre = -INFINITY;
        int j = c - 1;
        while (j >= 0) {
            unsigned f;
            do { f = ld_acquire(&g_f1[b*NCH + j]); } while (f == 0);
            if (f == 2) { pre = fmaxf(pre, g_incmax[b*NCH + j]); break; }
            pre = fmaxf(pre, g_aggmax[b*NCH + j]);
            j--;
        }
        g_incmax[bc] = fmaxf(pre, own);
        __threadfence();
        st_release(&g_f1[bc], 2);
        sbc[1] = pre;
    }
    __syncthreads();
    float preM = sbc[1];

    // --- e = exp(l - runmax), cumsum + sum lookback ---
    float M = fmaxf(lm, preM);
    float e = expf(l - M);
    se[tid] = e;
    float cs = iscan512<false>(e, ws);
    if (tid == 511) sbc[0] = cs;
    __syncthreads();
    if (tid == 0) {
        float own = sbc[0];
        g_aggsum[bc] = own;
        __threadfence();
        st_release(&g_f2[bc], 1);
        float pre = 0.f;
        int j = c - 1;
        while (j >= 0) {
            unsigned f;
            do { f = ld_acquire(&g_f2[b*NCH + j]); } while (f == 0);
            if (f == 2) { pre += g_incsum[b*NCH + j]; break; }
            pre += g_aggsum[b*NCH + j];
            j--;
        }
        g_incsum[bc] = pre + own;
        __threadfence();
        st_release(&g_f2[bc], 2);
        sbc[1] = pre;
    }
    __syncthreads();
    float preS = sbc[1];
    sr[tid] = 1.f / (cs + preS);
    __syncthreads();

    // --- channel partial sums of e*x (4 quarters x 128 channels) ---
    int d = tid & 127, q = tid >> 7;
    const float* xq = x + (base + q*128)*DD + d;
    {
        float acc = 0.f;
        #pragma unroll 4
        for (int t = 0; t < 128; t++) acc += se[q*128 + t] * xq[(size_t)t*DD];
        sP[q*128 + d] = acc;
    }
    __syncthreads();
    if (tid < 128) {
        float v = sP[d] + sP[128 + d] + sP[256 + d] + sP[384 + d];
        g_aggch[bc*DD + d] = v;
        sAgg[d] = v;
        __threadfence();
    }
    __syncthreads();
    if (tid == 0) st_release(&g_f3[bc], 1);

    // --- channel vector lookback (128 threads, per-channel) ---
    if (tid < 128) {
        float pre = 0.f;
        int j = c - 1;
        while (j >= 0) {
            unsigned f;
            do { f = ld_acquire(&g_f3[b*NCH + j]); } while (f == 0);
            if (f == 2) { pre += g_incch[(b*NCH + j)*DD + d]; break; }
            pre += g_aggch[(b*NCH + j)*DD + d];
            j--;
        }
        g_incch[bc*DD + d] = pre + sAgg[d];
        sPre[d] = pre;
        __threadfence();
    }
    __syncthreads();
    if (tid == 0) st_release(&g_f3[bc], 2);

    // --- final: prefix = cumsum(e*x)*r + x -> fp16 hi/lo ---
    float run = sPre[d];
    for (int qq = 0; qq < q; qq++) run += sP[qq*128 + d];
    __half* ph = g_ph + (base + q*128)*DD + d;
    __half* pl = g_pl + (base + q*128)*DD + d;
    #pragma unroll 4
    for (int t = 0; t < 128; t++) {
        float xv = xq[(size_t)t*DD];
        run += se[q*128 + t] * xv;
        float pv = run * sr[q*128 + t] + xv;
        __half h = __float2half(pv);
        ph[(size_t)t*DD] = h;
        pl[(size_t)t*DD] = __float2half(pv - __half2float(h));
    }
}

// ---------------- K4: conv1d via mma.sync fp16 single-pass (xh*wh) ----------
#define PITCH 272
#define A_OFF 0
#define W_OFF 71040
#define WSZ   34816
#define CONV_SMEM (W_OFF + 3*WSZ)
__device__ __forceinline__ void conv_issueW(int k, uint32_t dstbase, int tid) {
    #pragma unroll
    for (int u = 0; u < 4; u++) {
        int t = tid + u*512;
        int o = t >> 4, cc = (t & 15) << 3;
        cpa16(dstbase + o*PITCH + cc*2, g_wh + (((size_t)(k*128 + o)) << 7) + cc);
    }
}
__global__ __launch_bounds__(512, 1) void k_conv(const float* __restrict__ cb) {
    extern __shared__ char sm[];
    uint32_t sb = smem_u32(sm);
    int tid = threadIdx.x, lane = tid & 31, wid = tid >> 5;
    int wm = wid >> 1, wn = wid & 1;
    int nb = blockIdx.x >> 1;
    int p0loc = (blockIdx.x & 1) << 8;
    int lr = lane & 15, lh = lane >> 4;

    float c[2][8][4];
    #pragma unroll
    for (int mt = 0; mt < 2; mt++)
        #pragma unroll
        for (int nt = 0; nt < 8; nt++)
            #pragma unroll
            for (int v = 0; v < 4; v++) c[mt][nt][v] = 0.f;

    for (int t = tid; t < 261*16; t += 512) {
        int r = t >> 4, cc = (t & 15) << 3;
        int qq = p0loc + r - 2;
        const void* src = g_ph;
        int sz = 0;
        if (qq >= 0 && qq < 512) {
            src = g_ph + ((((size_t)nb << 9) + qq) << 7) + cc;
            sz = 16;
        }
        cpa16z(sb + A_OFF + r*PITCH + cc*2, src, sz);
    }
    CPA_COMMIT();
    const int nst = 6;
    #pragma unroll
    for (int s = 0; s < 3; s++) {
        conv_issueW(s, sb + W_OFF + s*WSZ, tid);
        CPA_COMMIT();
    }
    CPA_WAIT(2);
    __syncthreads();
    for (int s = 0; s < nst; s++) {
        int k = s;
        uint32_t abase = sb + A_OFF + (wm*32 + k + lr)*PITCH + lh*16;
        uint32_t bbase = sb + W_OFF + (s % 3)*WSZ + (wn*64 + lr)*PITCH + lh*16;
        #pragma unroll
        for (int kc = 0; kc < 8; kc++) {
            uint32_t a[2][4];
            ldsm_x4(a[0], abase + kc*32);
            ldsm_x4(a[1], abase + kc*32 + 16*PITCH);
            #pragma unroll
            for (int ntp = 0; ntp < 4; ntp++) {
                uint32_t bf[4];
                ldsm_x4(bf, bbase + ntp*16*PITCH + kc*32);
                #pragma unroll
                for (int mt = 0; mt < 2; mt++) {
                    mma16816(c[mt][2*ntp],     a[mt], bf[0], bf[2]);
                    mma16816(c[mt][2*ntp + 1], a[mt], bf[1], bf[3]);
                }
            }
        }
        __syncthreads();
        if (s + 3 < nst) {
            conv_issueW(s + 3, sb + W_OFF + ((s+3) % 3)*WSZ, tid);
            CPA_COMMIT();
        }
        if (s + 1 < nst) {
            CPA_WAIT(2);
            __syncthreads();
        }
    }
    CPA_WAIT(0);
    __syncthreads();

    int pbase = nb*512 + p0loc + wm*32 + (lane >> 2);
    #pragma unroll
    for (int nt = 0; nt < 8; nt++) {
        int col = wn*64 + nt*8 + (lane & 3)*2;
        float2 b2 = *(const float2*)(cb + col);
        float mx = -INFINITY, my = -INFINITY;
        #pragma unroll
        for (int mt = 0; mt < 2; mt++) {
            float x0 = c[mt][nt][0] + b2.x, y0 = c[mt][nt][1] + b2.y;
            float x1 = c[mt][nt][2] + b2.x, y1 = c[mt][nt][3] + b2.y;
            int row = pbase + mt*16;
            *(float2*)(g_conv + ((size_t)row << 7) + col)       = make_float2(x0, y0);
            *(float2*)(g_conv + ((size_t)(row + 8) << 7) + col) = make_float2(x1, y1);
            mx = fmaxf(mx, fmaxf(x0, x1));
            my = fmaxf(my, fmaxf(y0, y1));
        }
        #pragma unroll
        for (int o = 4; o < 32; o <<= 1) {
            mx = fmaxf(mx, __shfl_xor_sync(~0u, mx, o));
            my = fmaxf(my, __shfl_xor_sync(~0u, my, o));
        }
        if (lane < 4) {
            int cg = wn*64 + nt*8 + lane*2;
            atomicMax(&g_repr[nb*DD + cg],     enc_f(mx));
            atomicMax(&g_repr[nb*DD + cg + 1], enc_f(my));
        }
    }
}

// ---------------- K6: a_s, smem-cached KV + online softmax over 2 halves ----------
#define ATTNS_SMEM (256*128*4)
__global__ __launch_bounds__(256, 1) void k_attn_s() {
    extern __shared__ float sv[];      // 256 rows x 128 ch
    __shared__ float ss[256];
    __shared__ float red[256];
    int n = blockIdx.x, tid = threadIdx.x;
    int lane = tid & 31, wid = tid >> 5;
    int d = tid & 127, qh = tid >> 7;
    float4 q4;
    q4.x = dec_f(g_repr[n*DD + lane*4 + 0]);
    q4.y = dec_f(g_repr[n*DD + lane*4 + 1]);
    q4.z = dec_f(g_repr[n*DD + lane*4 + 2]);
    q4.w = dec_f(g_repr[n*DD + lane*4 + 3]);
    float M = -INFINITY, SUM = 0.f, acc = 0.f;
    for (int h = 0; h < 2; h++) {
        __syncthreads();
        const float* kv = g_conv + ((size_t)n*BSB + h*256)*DD;
        for (int i = tid*4; i < 256*128; i += 1024)
            *(float4*)&sv[i] = *(const float4*)&kv[i];
        __syncthreads();
        for (int j = wid; j < 256; j += 8) {
            float4 k4 = *(const float4*)&sv[j*DD + lane*4];
            float p = q4.x*k4.x + q4.y*k4.y + q4.z*k4.z + q4.w*k4.w;
            #pragma unroll
            for (int o = 16; o; o >>= 1) p += __shfl_xor_sync(~0u, p, o);
            if (lane == 0) ss[j] = p * SCALEF;
        }
        __syncthreads();
        red[tid] = ss[tid]; __syncthreads();
        for (int st = 128; st; st >>= 1) { if (tid < st) red[tid] = fmaxf(red[tid], red[tid+st]); __syncthreads(); }
        float Mn = fmaxf(M, red[0]);
        float sc = expf(M - Mn);
        acc *= sc; SUM *= sc; M = Mn;
        __syncthreads();
        float wgt = expf(ss[tid] - M);
        ss[tid] = wgt;
        red[tid] = wgt;
        __syncthreads();
        for (int st = 128; st; st >>= 1) { if (tid < st) red[tid] += red[tid+st]; __syncthreads(); }
        SUM += red[0];
        __syncthreads();
        #pragma unroll 4
        for (int t = 0; t < 128; t++) {
            int row = qh*128 + t;
            acc += ss[row] * sv[row*DD + d];
        }
    }
    __syncthreads();
    red[tid] = acc;
    __syncthreads();
    if (tid < 128) g_as[n*DD + tid] = (red[tid] + red[tid + 128]) / SUM;
}

// ---------------- K7: a_o = attn(block_repr, xbo, xbo) ----------------
__global__ void k_attn_o() {
    int n = blockIdx.x, tid = threadIdx.x;
    int lane = tid & 31, w = tid >> 5;
    int bq = n >> 6, c = n & 63;
    __shared__ float s[128];
    __shared__ float red[128];
    float qa[4];
    #pragma unroll
    for (int q = 0; q < 4; q++) qa[q] = dec_f(g_repr[n*DD + lane*4 + q]);
    for (int j = w; j < 128; j += 4) {
        int tt = 448 + c*BSB + j; if (tt > LTOK-1) tt = LTOK-1;
        size_t ro = ((size_t)bq*LTOK + tt) << 7;
        float p = 0.f;
        #pragma unroll
        for (int q = 0; q < 4; q++) {
            int chn = lane*4 + q;
            float kvv = __half2float(g_ph[ro + chn]) + __half2float(g_pl[ro + chn]);
            p += qa[q] * kvv;
        }
        #pragma unroll
        for (int o = 16; o; o >>= 1) p += __shfl_xor_sync(~0u, p, o);
        if (lane == 0) s[j] = p * SCALEF;
    }
    __syncthreads();
    red[tid] = s[tid]; __syncthreads();
    for (int st = 64; st; st >>= 1) { if (tid < st) red[tid] = fmaxf(red[tid], red[tid+st]); __syncthreads(); }
    float M = red[0]; __syncthreads();
    float e = expf(s[tid] - M); s[tid] = e;
    red[tid] = e; __syncthreads();
    for (int st = 64; st; st >>= 1) { if (tid < st) red[tid] += red[tid+st]; __syncthreads(); }
    float SUM = red[0]; __syncthreads();
    float acc = 0.f;
    for (int j = 0; j < 128; j++) {
        int tt = 448 + c*BSB + j; if (tt > LTOK-1) tt = LTOK-1;
        size_t ro = ((size_t)bq*LTOK + tt) << 7;
        acc += s[j] * (__half2float(g_ph[ro + tid]) + __half2float(g_pl[ro + tid]));
    }
    g_ao[n*DD + tid] = acc / SUM;
}

// ---------------- K8: fusion GEMV ----------------
__global__ void k_fuse(const float* __restrict__ fw, const float* __restrict__ fb,
                       float* __restrict__ out, int out_size) {
    int n = blockIdx.x, o = threadIdx.x;
    __shared__ float f[384];
    f[o]       = g_as[n*DD + o];
    f[128 + o] = g_ao[n*DD + o];
    f[256 + o] = dec_f(g_repr[n*DD + o]);
    __syncthreads();
    float acc = fb[o];
    #pragma unroll 4
    for (int i = 0; i < 384; i++) acc += f[i] * fw[i*DD + o];
    for (int off = 0; off + NBL*DD <= out_size; off += NBL*DD)
        out[off + n*DD + o] = acc;
}

// ---------------- launch ----------------
extern "C" void kernel_launch(void* const* d_in, const int* in_sizes, int n_in,
                              void* d_out, int out_size) {
    const float* x        = (const float*)d_in[0];
    const float* w_lw     = (const float*)d_in[1];
    const float* b_lw     = (const float*)d_in[2];
    const float* conv_w   = (const float*)d_in[3];
    const float* conv_b   = (const float*)d_in[4];
    const float* fusion_w = (const float*)d_in[5];
    const float* fusion_b = (const float*)d_in[6];
    float* out = (float*)d_out;

    cudaFuncSetAttribute(k_conv, cudaFuncAttributeMaxDynamicSharedMemorySize, CONV_SMEM);
    cudaFuncSetAttribute(k_attn_s, cudaFuncAttributeMaxDynamicSharedMemorySize, ATTNS_SMEM);

    k_wt<<<96, 1024>>>(conv_w);
    k_init<<<64, 1024>>>();
    k_pre<<<dim3(NCH, BB), 512>>>(x, w_lw, b_lw);
    k_conv<<<1024, 512, CONV_SMEM>>>(conv_b);
    k_attn_s<<<NBL, 256, ATTNS_SMEM>>>();
    k_attn_o<<<NBL, 128>>>();
    k_fuse<<<NBL, 128>>>(fusion_w, fusion_b, out, out_size);
}